// round 5
// baseline (speedup 1.0000x reference)
#include <cuda_runtime.h>
#include <cuda_bf16.h>
#include <math.h>
#include <stdint.h>

// Problem constants
#define BSZ   512
#define DD    64
#define DE    65
#define JK    4225      // 65*65
#define NOUT  256
#define KTOT  274625    // 65^3
#define ZSPLIT 18
#define NCH_TOT 8583    // ceil(274625/32)
#define CH_PER 477      // ceil(8583/18)

// Scratch (static device arrays only)
__device__ float g_oe[3 * BSZ * DE];            // o1e/o2e/o3e with appended 1.0
__device__ float g_P[BSZ * JK];                 // P[b][jk] = o2e[b][j]*o3e[b][k]
__device__ float g_part[ZSPLIT * BSZ * NOUT];   // split-K partials [z][b][o]
__device__ float g_E[BSZ * 456];                // enc2 input [relu(enc1)|skips|pad]

struct Ptrs { const float* p[25]; };

__device__ __forceinline__ unsigned long long dup2(float x) {
    unsigned long long r;
    asm("mov.b64 %0, {%1, %1};" : "=l"(r) : "r"(__float_as_uint(x)));
    return r;
}
__device__ __forceinline__ void fma2(unsigned long long& acc, unsigned long long a, unsigned long long b) {
    asm("fma.rn.f32x2 %0, %1, %2, %0;" : "+l"(acc) : "l"(a), "l"(b));
}

__device__ __forceinline__ void mma_bf16(float* d, const uint32_t* a, const uint32_t* b) {
    asm volatile("mma.sync.aligned.m16n8k16.row.col.f32.bf16.bf16.f32 "
        "{%0,%1,%2,%3}, {%4,%5,%6,%7}, {%8,%9}, {%0,%1,%2,%3};"
        : "+f"(d[0]), "+f"(d[1]), "+f"(d[2]), "+f"(d[3])
        : "r"(a[0]), "r"(a[1]), "r"(a[2]), "r"(a[3]), "r"(b[0]), "r"(b[1]));
}

// ---------------------------------------------------------------------------
// Kernel 1: three gated branches -> o1e/o2e/o3e [512][65] (last col = 1.0)
// ---------------------------------------------------------------------------
__global__ __launch_bounds__(256) void k_branches(Ptrs P) {
    __shared__ float vs[3][16][DD];
    __shared__ float gs[16][DD];
    int b0 = blockIdx.x * 16;
    int t = threadIdx.x;

    for (int e = t; e < 16 * DD; e += 256) {
        int bb = e >> 6, m = e & 63;
        vs[0][bb][m] = P.p[0][(b0 + bb) * DD + m];
        vs[1][bb][m] = P.p[1][(b0 + bb) * DD + m];
        vs[2][bb][m] = P.p[2][(b0 + bb) * DD + m];
    }
    __syncthreads();

    int o = t & 63, bg = t >> 6;
    for (int br = 0; br < 3; ++br) {
        const float* hw = P.p[3 + br * 6];
        const float* hb = P.p[4 + br * 6];
        const float* zw = P.p[5 + br * 6];
        const float* zb = P.p[6 + br * 6];
        const float* ow = P.p[7 + br * 6];
        const float* ob = P.p[8 + br * 6];
        int hv = br;
        int x1 = (br == 1) ? 1 : 0;

        float hacc[4], zacc[4];
        #pragma unroll
        for (int q = 0; q < 4; q++) { hacc[q] = hb[o]; zacc[q] = zb[o]; }

        const float* hwr = hw + o * DD;
        #pragma unroll 8
        for (int m = 0; m < DD; m++) {
            float w = hwr[m];
            #pragma unroll
            for (int q = 0; q < 4; q++) hacc[q] += w * vs[hv][bg * 4 + q][m];
        }

        for (int i = 0; i < DD; i++) {
            float s[4] = {0.f, 0.f, 0.f, 0.f};
            const float* zr = zw + o * DD * DD + i * DD;
            #pragma unroll 8
            for (int j = 0; j < DD; j++) {
                float w = zr[j];
                #pragma unroll
                for (int q = 0; q < 4; q++) s[q] += w * vs[2][bg * 4 + q][j];
            }
            #pragma unroll
            for (int q = 0; q < 4; q++) zacc[q] += vs[x1][bg * 4 + q][i] * s[q];
        }

        #pragma unroll
        for (int q = 0; q < 4; q++) {
            float h = fmaxf(hacc[q], 0.f);
            float sg = 1.f / (1.f + expf(-zacc[q]));
            gs[bg * 4 + q][o] = h * sg;
        }
        __syncthreads();

        float oacc[4];
        #pragma unroll
        for (int q = 0; q < 4; q++) oacc[q] = ob[o];
        const float* owr = ow + o * DD;
        #pragma unroll 8
        for (int m = 0; m < DD; m++) {
            float w = owr[m];
            #pragma unroll
            for (int q = 0; q < 4; q++) oacc[q] += w * gs[bg * 4 + q][m];
        }
        #pragma unroll
        for (int q = 0; q < 4; q++) {
            g_oe[((long long)br * BSZ + b0 + bg * 4 + q) * DE + o] = fmaxf(oacc[q], 0.f);
            if (o == 0) g_oe[((long long)br * BSZ + b0 + bg * 4 + q) * DE + DD] = 1.f;
        }
        __syncthreads();
    }
}

// ---------------------------------------------------------------------------
// Kernel 2: P[b][j*65+k] = o2e[b][j] * o3e[b][k]
// ---------------------------------------------------------------------------
__global__ __launch_bounds__(256) void k_pair() {
    int b = blockIdx.x, t = threadIdx.x;
    __shared__ float s2[DE], s3[DE];
    if (t < DE)           s2[t]      = g_oe[(1 * BSZ + b) * DE + t];
    else if (t < 2 * DE)  s3[t - DE] = g_oe[(2 * BSZ + b) * DE + (t - DE)];
    __syncthreads();
    for (int e = t; e < JK; e += 256) {
        int j = e / DE, k = e - j * DE;
        g_P[b * JK + e] = s2[j] * s3[k];
    }
}

// ---------------------------------------------------------------------------
// Kernel 3: big GEMM via mma.sync bf16 3-pass (base-PTX tensor path).
// C[o 256, b 512] = sum_kb W[o,kb] * Bmat[kb,b], Bmat = o1e[b,i]*P[b,jk].
// CTA tile 128(o) x 128(b), chunk = 32 k, grid (4 btiles, 2 otiles, 18 splits).
// ---------------------------------------------------------------------------
#define SROW     80                 // bytes per smem row (40 bf16, conflict-free pad)
#define O1_BYTES (128 * 66 * 4)     // 33792
#define STAGE_SZ 40960              // 4 planes * 128 rows * 80 B
#define AH_OFF   0
#define AL_OFF   10240
#define BH_OFF   20480
#define BL_OFF   30720
#define SMEM_GEMM (O1_BYTES + 2 * STAGE_SZ)

__global__ __launch_bounds__(256, 1) void k_gemm_mma(const float* __restrict__ W) {
    extern __shared__ char smem[];
    float* o1s = (float*)smem;                       // [128][66]
    const int t = threadIdx.x, w = t >> 5, lane = t & 31;
    const int gid = lane >> 2, tig = lane & 3;
    const int warp_m = w >> 2, warp_n = w & 3;
    const int b0 = blockIdx.x * 128, o0 = blockIdx.y * 128, z = blockIdx.z;

    // cache o1e for this CTA's b-range
    for (int e = t; e < 128 * DE; e += 256) {
        int bl = e / DE, ii = e - bl * DE;
        o1s[bl * 66 + ii] = g_oe[(b0 + bl) * DE + ii];
    }
    __syncthreads();

    const int c0 = z * CH_PER;
    const int nch = min(c0 + CH_PER, NCH_TOT) - c0;

    float acc[4][4][4];
    #pragma unroll
    for (int mt = 0; mt < 4; mt++)
        #pragma unroll
        for (int nt = 0; nt < 4; nt++)
            #pragma unroll
            for (int q = 0; q < 4; q++) acc[mt][nt][q] = 0.f;

    float aR[16], bR[16];

    // prefetch chunk c0
    {
        int kb = c0 * 32 + lane;
        bool ok = kb < KTOT;
        int kk = ok ? kb : 0;
        int i = kk / JK, jk = kk - i * JK;
        const float* wp = W + (size_t)(o0 + w * 16) * KTOT + kk;
        const float* pp = g_P + (size_t)(b0 + w * 16) * JK + jk;
        #pragma unroll
        for (int r = 0; r < 16; r++) {
            aR[r] = ok ? __ldg(wp + (size_t)r * KTOT) : 0.f;
            bR[r] = ok ? __ldg(pp + (size_t)r * JK) : 0.f;
        }
    }

    for (int ci = 0; ci < nch; ++ci) {
        const int s = ci & 1;
        char* st = smem + O1_BYTES + s * STAGE_SZ;

        // store prefetched chunk to smem as bf16 hi/lo planes
        {
            int kb = (c0 + ci) * 32 + lane;
            int kk = (kb < KTOT) ? kb : 0;
            int i = kk / JK;
            uint32_t off = (uint32_t)(w * 16) * SROW + lane * 2;
            #pragma unroll
            for (int r = 0; r < 16; r++) {
                float v = aR[r];
                __nv_bfloat16 h = __float2bfloat16(v);
                __nv_bfloat16 l = __float2bfloat16(v - __bfloat162float(h));
                *(__nv_bfloat16*)(st + AH_OFF + off + r * SROW) = h;
                *(__nv_bfloat16*)(st + AL_OFF + off + r * SROW) = l;
                float u = bR[r] * o1s[(w * 16 + r) * 66 + i];
                __nv_bfloat16 h2 = __float2bfloat16(u);
                __nv_bfloat16 l2 = __float2bfloat16(u - __bfloat162float(h2));
                *(__nv_bfloat16*)(st + BH_OFF + off + r * SROW) = h2;
                *(__nv_bfloat16*)(st + BL_OFF + off + r * SROW) = l2;
            }
        }
        __syncthreads();

        // prefetch next chunk (hidden under mma below)
        if (ci + 1 < nch) {
            int kb = (c0 + ci + 1) * 32 + lane;
            bool ok = kb < KTOT;
            int kk = ok ? kb : 0;
            int i = kk / JK, jk = kk - i * JK;
            const float* wp = W + (size_t)(o0 + w * 16) * KTOT + kk;
            const float* pp = g_P + (size_t)(b0 + w * 16) * JK + jk;
            #pragma unroll
            for (int r = 0; r < 16; r++) {
                aR[r] = ok ? __ldg(wp + (size_t)r * KTOT) : 0.f;
                bR[r] = ok ? __ldg(pp + (size_t)r * JK) : 0.f;
            }
        }

        // compute on stage s
        {
            const char* sc = smem + O1_BYTES + s * STAGE_SZ;
            #pragma unroll
            for (int kh = 0; kh < 2; ++kh) {
                uint32_t ah[4][4], al[4][4], bh[4][2], bl[4][2];
                #pragma unroll
                for (int mt = 0; mt < 4; mt++) {
                    uint32_t r0 = (uint32_t)(warp_m * 64 + mt * 16 + gid) * SROW + tig * 4 + kh * 32;
                    ah[mt][0] = *(const uint32_t*)(sc + AH_OFF + r0);
                    ah[mt][1] = *(const uint32_t*)(sc + AH_OFF + r0 + 8 * SROW);
                    ah[mt][2] = *(const uint32_t*)(sc + AH_OFF + r0 + 16);
                    ah[mt][3] = *(const uint32_t*)(sc + AH_OFF + r0 + 8 * SROW + 16);
                    al[mt][0] = *(const uint32_t*)(sc + AL_OFF + r0);
                    al[mt][1] = *(const uint32_t*)(sc + AL_OFF + r0 + 8 * SROW);
                    al[mt][2] = *(const uint32_t*)(sc + AL_OFF + r0 + 16);
                    al[mt][3] = *(const uint32_t*)(sc + AL_OFF + r0 + 8 * SROW + 16);
                }
                #pragma unroll
                for (int nt = 0; nt < 4; nt++) {
                    uint32_t r0 = (uint32_t)(warp_n * 32 + nt * 8 + gid) * SROW + tig * 4 + kh * 32;
                    bh[nt][0] = *(const uint32_t*)(sc + BH_OFF + r0);
                    bh[nt][1] = *(const uint32_t*)(sc + BH_OFF + r0 + 16);
                    bl[nt][0] = *(const uint32_t*)(sc + BL_OFF + r0);
                    bl[nt][1] = *(const uint32_t*)(sc + BL_OFF + r0 + 16);
                }
                #pragma unroll
                for (int mt = 0; mt < 4; mt++)
                    #pragma unroll
                    for (int nt = 0; nt < 4; nt++)
                        mma_bf16(acc[mt][nt], ah[mt], bh[nt]);
                #pragma unroll
                for (int mt = 0; mt < 4; mt++)
                    #pragma unroll
                    for (int nt = 0; nt < 4; nt++)
                        mma_bf16(acc[mt][nt], al[mt], bh[nt]);
                #pragma unroll
                for (int mt = 0; mt < 4; mt++)
                    #pragma unroll
                    for (int nt = 0; nt < 4; nt++)
                        mma_bf16(acc[mt][nt], ah[mt], bl[nt]);
            }
        }
    }

    // epilogue: acc -> g_part[z][b][o]
    float* gp = g_part + (size_t)z * BSZ * NOUT;
    #pragma unroll
    for (int mt = 0; mt < 4; mt++) {
        int o = o0 + warp_m * 64 + mt * 16 + gid;
        #pragma unroll
        for (int nt = 0; nt < 4; nt++) {
            int b = b0 + warp_n * 32 + nt * 8 + tig * 2;
            gp[(size_t)b * NOUT + o]           = acc[mt][nt][0];
            gp[(size_t)(b + 1) * NOUT + o]     = acc[mt][nt][1];
            gp[(size_t)b * NOUT + o + 8]       = acc[mt][nt][2];
            gp[(size_t)(b + 1) * NOUT + o + 8] = acc[mt][nt][3];
        }
    }
}

// ---------------------------------------------------------------------------
// Kernel 4: reduce split-K partials + enc1 bias/relu + build enc2 input
// ---------------------------------------------------------------------------
__global__ __launch_bounds__(256) void k_reduce(const float* __restrict__ e1b) {
    int b = blockIdx.x, t = threadIdx.x;
    float s = e1b[t];
    #pragma unroll 6
    for (int zz = 0; zz < ZSPLIT; ++zz)
        s += g_part[((size_t)zz * BSZ + b) * NOUT + t];
    g_E[b * 456 + t] = fmaxf(s, 0.f);
    if (t < 195)
        g_E[b * 456 + 256 + t] = g_oe[((t / 65) * BSZ + b) * DE + (t % 65)];
    else if (t < 200)
        g_E[b * 456 + 451 + (t - 195)] = 0.f;
}

// ---------------------------------------------------------------------------
// Kernel 5: enc2 tiled GEMM: out[b,n] = relu(E[b,:451] . e2w[n,:451] + e2b[n])
// ---------------------------------------------------------------------------
__global__ __launch_bounds__(256) void k_enc2(const float* __restrict__ e2w,
                                              const float* __restrict__ e2b,
                                              float* __restrict__ out) {
    __shared__ __align__(16) float As[64][68];
    __shared__ __align__(16) float Bs[64][68];
    int b0 = blockIdx.x * 64, n0 = blockIdx.y * 64;
    int t = threadIdx.x;
    int m0 = (t >> 4) << 2, q0 = (t & 15) << 2;

    unsigned long long acc[4][2];
    #pragma unroll
    for (int a = 0; a < 4; a++)
        #pragma unroll
        for (int p = 0; p < 2; p++) acc[a][p] = 0ull;

    for (int kc = 0; kc < 512; kc += 64) {
        __syncthreads();
        for (int e = t; e < 64 * 64; e += 256) {
            int r = e >> 6, kk = e & 63;
            int k = kc + kk;
            As[kk][r] = (k < 451) ? e2w[(n0 + r) * 451 + k] : 0.f;
            Bs[kk][r] = (k < 451) ? g_E[(b0 + r) * 456 + k] : 0.f;
        }
        __syncthreads();
        #pragma unroll 16
        for (int kk = 0; kk < 64; ++kk) {
            float4 a4 = *(const float4*)&As[kk][m0];
            ulonglong2 bb = *(const ulonglong2*)&Bs[kk][q0];
            unsigned long long a0 = dup2(a4.x), a1 = dup2(a4.y),
                               a2 = dup2(a4.z), a3 = dup2(a4.w);
            fma2(acc[0][0], a0, bb.x); fma2(acc[0][1], a0, bb.y);
            fma2(acc[1][0], a1, bb.x); fma2(acc[1][1], a1, bb.y);
            fma2(acc[2][0], a2, bb.x); fma2(acc[2][1], a2, bb.y);
            fma2(acc[3][0], a3, bb.x); fma2(acc[3][1], a3, bb.y);
        }
    }

    #pragma unroll
    for (int mi = 0; mi < 4; ++mi) {
        int n = n0 + m0 + mi;
        float bias = e2b[n];
        #pragma unroll
        for (int p = 0; p < 2; ++p) {
            unsigned long long v = acc[mi][p];
            float lo = __uint_as_float((unsigned)v);
            float hi = __uint_as_float((unsigned)(v >> 32));
            out[(b0 + q0 + 2 * p)     * NOUT + n] = fmaxf(lo + bias, 0.f);
            out[(b0 + q0 + 2 * p + 1) * NOUT + n] = fmaxf(hi + bias, 0.f);
        }
    }
}

// ---------------------------------------------------------------------------
extern "C" void kernel_launch(void* const* d_in, const int* in_sizes, int n_in,
                              void* d_out, int out_size) {
    Ptrs P;
    for (int i = 0; i < 25; i++) P.p[i] = (const float*)d_in[i];

    cudaFuncSetAttribute(k_gemm_mma, cudaFuncAttributeMaxDynamicSharedMemorySize, SMEM_GEMM);

    k_branches<<<32, 256>>>(P);
    k_pair<<<512, 256>>>();
    k_gemm_mma<<<dim3(4, 2, ZSPLIT), 256, SMEM_GEMM>>>((const float*)d_in[21]);
    k_reduce<<<512, 256>>>((const float*)d_in[22]);
    k_enc2<<<dim3(8, 4), 256>>>((const float*)d_in[23], (const float*)d_in[24], (float*)d_out);
}

// round 6
// speedup vs baseline: 1.0006x; 1.0006x over previous
#include <cuda_runtime.h>
#include <cuda_bf16.h>
#include <math.h>
#include <stdint.h>

// Problem constants
#define BSZ   512
#define DD    64
#define DE    65
#define JK    4225      // 65*65
#define NOUT  256
#define KTOT  274625    // 65^3
#define ZSPLIT 18
#define NCH_TOT 8583    // ceil(274625/32)
#define CH_PER 477      // ceil(8583/18)

// Scratch (static device arrays only)
__device__ float g_oe[3 * BSZ * DE];            // o1e/o2e/o3e with appended 1.0
__device__ float g_P[BSZ * JK];                 // P[b][jk] = o2e[b][j]*o3e[b][k]
__device__ float g_part[ZSPLIT * BSZ * NOUT];   // split-K partials [z][b][o]
__device__ float g_E[BSZ * 456];                // enc2 input [relu(enc1)|skips|pad]

struct Ptrs { const float* p[25]; };

__device__ __forceinline__ unsigned long long dup2(float x) {
    unsigned long long r;
    asm("mov.b64 %0, {%1, %1};" : "=l"(r) : "r"(__float_as_uint(x)));
    return r;
}
__device__ __forceinline__ void fma2(unsigned long long& acc, unsigned long long a, unsigned long long b) {
    asm("fma.rn.f32x2 %0, %1, %2, %0;" : "+l"(acc) : "l"(a), "l"(b));
}

__device__ __forceinline__ void mma_bf16(float* d, const uint32_t* a, const uint32_t* b) {
    asm volatile("mma.sync.aligned.m16n8k16.row.col.f32.bf16.bf16.f32 "
        "{%0,%1,%2,%3}, {%4,%5,%6,%7}, {%8,%9}, {%0,%1,%2,%3};"
        : "+f"(d[0]), "+f"(d[1]), "+f"(d[2]), "+f"(d[3])
        : "r"(a[0]), "r"(a[1]), "r"(a[2]), "r"(a[3]), "r"(b[0]), "r"(b[1]));
}

// ---------------------------------------------------------------------------
// Kernel 1: three gated branches -> o1e/o2e/o3e [512][65] (last col = 1.0)
// ---------------------------------------------------------------------------
__global__ __launch_bounds__(256) void k_branches(Ptrs P) {
    __shared__ float vs[3][16][DD];
    __shared__ float gs[16][DD];
    int b0 = blockIdx.x * 16;
    int t = threadIdx.x;

    for (int e = t; e < 16 * DD; e += 256) {
        int bb = e >> 6, m = e & 63;
        vs[0][bb][m] = P.p[0][(b0 + bb) * DD + m];
        vs[1][bb][m] = P.p[1][(b0 + bb) * DD + m];
        vs[2][bb][m] = P.p[2][(b0 + bb) * DD + m];
    }
    __syncthreads();

    int o = t & 63, bg = t >> 6;
    for (int br = 0; br < 3; ++br) {
        const float* hw = P.p[3 + br * 6];
        const float* hb = P.p[4 + br * 6];
        const float* zw = P.p[5 + br * 6];
        const float* zb = P.p[6 + br * 6];
        const float* ow = P.p[7 + br * 6];
        const float* ob = P.p[8 + br * 6];
        int hv = br;
        int x1 = (br == 1) ? 1 : 0;

        float hacc[4], zacc[4];
        #pragma unroll
        for (int q = 0; q < 4; q++) { hacc[q] = hb[o]; zacc[q] = zb[o]; }

        const float* hwr = hw + o * DD;
        #pragma unroll 8
        for (int m = 0; m < DD; m++) {
            float w = hwr[m];
            #pragma unroll
            for (int q = 0; q < 4; q++) hacc[q] += w * vs[hv][bg * 4 + q][m];
        }

        for (int i = 0; i < DD; i++) {
            float s[4] = {0.f, 0.f, 0.f, 0.f};
            const float* zr = zw + o * DD * DD + i * DD;
            #pragma unroll 8
            for (int j = 0; j < DD; j++) {
                float w = zr[j];
                #pragma unroll
                for (int q = 0; q < 4; q++) s[q] += w * vs[2][bg * 4 + q][j];
            }
            #pragma unroll
            for (int q = 0; q < 4; q++) zacc[q] += vs[x1][bg * 4 + q][i] * s[q];
        }

        #pragma unroll
        for (int q = 0; q < 4; q++) {
            float h = fmaxf(hacc[q], 0.f);
            float sg = 1.f / (1.f + expf(-zacc[q]));
            gs[bg * 4 + q][o] = h * sg;
        }
        __syncthreads();

        float oacc[4];
        #pragma unroll
        for (int q = 0; q < 4; q++) oacc[q] = ob[o];
        const float* owr = ow + o * DD;
        #pragma unroll 8
        for (int m = 0; m < DD; m++) {
            float w = owr[m];
            #pragma unroll
            for (int q = 0; q < 4; q++) oacc[q] += w * gs[bg * 4 + q][m];
        }
        #pragma unroll
        for (int q = 0; q < 4; q++) {
            g_oe[((long long)br * BSZ + b0 + bg * 4 + q) * DE + o] = fmaxf(oacc[q], 0.f);
            if (o == 0) g_oe[((long long)br * BSZ + b0 + bg * 4 + q) * DE + DD] = 1.f;
        }
        __syncthreads();
    }
}

// ---------------------------------------------------------------------------
// Kernel 2: P[b][j*65+k] = o2e[b][j] * o3e[b][k]
// ---------------------------------------------------------------------------
__global__ __launch_bounds__(256) void k_pair() {
    int b = blockIdx.x, t = threadIdx.x;
    __shared__ float s2[DE], s3[DE];
    if (t < DE)           s2[t]      = g_oe[(1 * BSZ + b) * DE + t];
    else if (t < 2 * DE)  s3[t - DE] = g_oe[(2 * BSZ + b) * DE + (t - DE)];
    __syncthreads();
    for (int e = t; e < JK; e += 256) {
        int j = e / DE, k = e - j * DE;
        g_P[b * JK + e] = s2[j] * s3[k];
    }
}

// ---------------------------------------------------------------------------
// Kernel 3: big GEMM via mma.sync bf16 3-pass (base-PTX tensor path).
// C[o 256, b 512] = sum_kb W[o,kb] * Bmat[kb,b], Bmat = o1e[b,i]*P[b,jk].
// CTA tile 128(o) x 128(b), chunk = 32 k, grid (4 btiles, 2 otiles, 18 splits).
// ---------------------------------------------------------------------------
#define SROW     80                 // bytes per smem row (40 bf16, conflict-free pad)
#define O1_BYTES (128 * 66 * 4)     // 33792
#define STAGE_SZ 40960              // 4 planes * 128 rows * 80 B
#define AH_OFF   0
#define AL_OFF   10240
#define BH_OFF   20480
#define BL_OFF   30720
#define SMEM_GEMM (O1_BYTES + 2 * STAGE_SZ)

__global__ __launch_bounds__(256, 1) void k_gemm_mma(const float* __restrict__ W) {
    extern __shared__ char smem[];
    float* o1s = (float*)smem;                       // [128][66]
    const int t = threadIdx.x, w = t >> 5, lane = t & 31;
    const int gid = lane >> 2, tig = lane & 3;
    const int warp_m = w >> 2, warp_n = w & 3;
    const int b0 = blockIdx.x * 128, o0 = blockIdx.y * 128, z = blockIdx.z;

    // cache o1e for this CTA's b-range
    for (int e = t; e < 128 * DE; e += 256) {
        int bl = e / DE, ii = e - bl * DE;
        o1s[bl * 66 + ii] = g_oe[(b0 + bl) * DE + ii];
    }
    __syncthreads();

    const int c0 = z * CH_PER;
    const int nch = min(c0 + CH_PER, NCH_TOT) - c0;

    float acc[4][4][4];
    #pragma unroll
    for (int mt = 0; mt < 4; mt++)
        #pragma unroll
        for (int nt = 0; nt < 4; nt++)
            #pragma unroll
            for (int q = 0; q < 4; q++) acc[mt][nt][q] = 0.f;

    float aR[16], bR[16];

    // prefetch chunk c0
    {
        int kb = c0 * 32 + lane;
        bool ok = kb < KTOT;
        int kk = ok ? kb : 0;
        int i = kk / JK, jk = kk - i * JK;
        const float* wp = W + (size_t)(o0 + w * 16) * KTOT + kk;
        const float* pp = g_P + (size_t)(b0 + w * 16) * JK + jk;
        #pragma unroll
        for (int r = 0; r < 16; r++) {
            aR[r] = ok ? __ldg(wp + (size_t)r * KTOT) : 0.f;
            bR[r] = ok ? __ldg(pp + (size_t)r * JK) : 0.f;
        }
    }

    for (int ci = 0; ci < nch; ++ci) {
        const int s = ci & 1;
        char* st = smem + O1_BYTES + s * STAGE_SZ;

        // store prefetched chunk to smem as bf16 hi/lo planes
        {
            int kb = (c0 + ci) * 32 + lane;
            int kk = (kb < KTOT) ? kb : 0;
            int i = kk / JK;
            uint32_t off = (uint32_t)(w * 16) * SROW + lane * 2;
            #pragma unroll
            for (int r = 0; r < 16; r++) {
                float v = aR[r];
                __nv_bfloat16 h = __float2bfloat16(v);
                __nv_bfloat16 l = __float2bfloat16(v - __bfloat162float(h));
                *(__nv_bfloat16*)(st + AH_OFF + off + r * SROW) = h;
                *(__nv_bfloat16*)(st + AL_OFF + off + r * SROW) = l;
                float u = bR[r] * o1s[(w * 16 + r) * 66 + i];
                __nv_bfloat16 h2 = __float2bfloat16(u);
                __nv_bfloat16 l2 = __float2bfloat16(u - __bfloat162float(h2));
                *(__nv_bfloat16*)(st + BH_OFF + off + r * SROW) = h2;
                *(__nv_bfloat16*)(st + BL_OFF + off + r * SROW) = l2;
            }
        }
        __syncthreads();

        // prefetch next chunk (hidden under mma below)
        if (ci + 1 < nch) {
            int kb = (c0 + ci + 1) * 32 + lane;
            bool ok = kb < KTOT;
            int kk = ok ? kb : 0;
            int i = kk / JK, jk = kk - i * JK;
            const float* wp = W + (size_t)(o0 + w * 16) * KTOT + kk;
            const float* pp = g_P + (size_t)(b0 + w * 16) * JK + jk;
            #pragma unroll
            for (int r = 0; r < 16; r++) {
                aR[r] = ok ? __ldg(wp + (size_t)r * KTOT) : 0.f;
                bR[r] = ok ? __ldg(pp + (size_t)r * JK) : 0.f;
            }
        }

        // compute on stage s
        {
            const char* sc = smem + O1_BYTES + s * STAGE_SZ;
            #pragma unroll
            for (int kh = 0; kh < 2; ++kh) {
                uint32_t ah[4][4], al[4][4], bh[4][2], bl[4][2];
                #pragma unroll
                for (int mt = 0; mt < 4; mt++) {
                    uint32_t r0 = (uint32_t)(warp_m * 64 + mt * 16 + gid) * SROW + tig * 4 + kh * 32;
                    ah[mt][0] = *(const uint32_t*)(sc + AH_OFF + r0);
                    ah[mt][1] = *(const uint32_t*)(sc + AH_OFF + r0 + 8 * SROW);
                    ah[mt][2] = *(const uint32_t*)(sc + AH_OFF + r0 + 16);
                    ah[mt][3] = *(const uint32_t*)(sc + AH_OFF + r0 + 8 * SROW + 16);
                    al[mt][0] = *(const uint32_t*)(sc + AL_OFF + r0);
                    al[mt][1] = *(const uint32_t*)(sc + AL_OFF + r0 + 8 * SROW);
                    al[mt][2] = *(const uint32_t*)(sc + AL_OFF + r0 + 16);
                    al[mt][3] = *(const uint32_t*)(sc + AL_OFF + r0 + 8 * SROW + 16);
                }
                #pragma unroll
                for (int nt = 0; nt < 4; nt++) {
                    uint32_t r0 = (uint32_t)(warp_n * 32 + nt * 8 + gid) * SROW + tig * 4 + kh * 32;
                    bh[nt][0] = *(const uint32_t*)(sc + BH_OFF + r0);
                    bh[nt][1] = *(const uint32_t*)(sc + BH_OFF + r0 + 16);
                    bl[nt][0] = *(const uint32_t*)(sc + BL_OFF + r0);
                    bl[nt][1] = *(const uint32_t*)(sc + BL_OFF + r0 + 16);
                }
                #pragma unroll
                for (int mt = 0; mt < 4; mt++)
                    #pragma unroll
                    for (int nt = 0; nt < 4; nt++)
                        mma_bf16(acc[mt][nt], ah[mt], bh[nt]);
                #pragma unroll
                for (int mt = 0; mt < 4; mt++)
                    #pragma unroll
                    for (int nt = 0; nt < 4; nt++)
                        mma_bf16(acc[mt][nt], al[mt], bh[nt]);
                #pragma unroll
                for (int mt = 0; mt < 4; mt++)
                    #pragma unroll
                    for (int nt = 0; nt < 4; nt++)
                        mma_bf16(acc[mt][nt], ah[mt], bl[nt]);
            }
        }
    }

    // epilogue: acc -> g_part[z][b][o]
    float* gp = g_part + (size_t)z * BSZ * NOUT;
    #pragma unroll
    for (int mt = 0; mt < 4; mt++) {
        int o = o0 + warp_m * 64 + mt * 16 + gid;
        #pragma unroll
        for (int nt = 0; nt < 4; nt++) {
            int b = b0 + warp_n * 32 + nt * 8 + tig * 2;
            gp[(size_t)b * NOUT + o]           = acc[mt][nt][0];
            gp[(size_t)(b + 1) * NOUT + o]     = acc[mt][nt][1];
            gp[(size_t)b * NOUT + o + 8]       = acc[mt][nt][2];
            gp[(size_t)(b + 1) * NOUT + o + 8] = acc[mt][nt][3];
        }
    }
}

// ---------------------------------------------------------------------------
// Kernel 4: reduce split-K partials + enc1 bias/relu + build enc2 input
// ---------------------------------------------------------------------------
__global__ __launch_bounds__(256) void k_reduce(const float* __restrict__ e1b) {
    int b = blockIdx.x, t = threadIdx.x;
    float s = e1b[t];
    #pragma unroll 6
    for (int zz = 0; zz < ZSPLIT; ++zz)
        s += g_part[((size_t)zz * BSZ + b) * NOUT + t];
    g_E[b * 456 + t] = fmaxf(s, 0.f);
    if (t < 195)
        g_E[b * 456 + 256 + t] = g_oe[((t / 65) * BSZ + b) * DE + (t % 65)];
    else if (t < 200)
        g_E[b * 456 + 451 + (t - 195)] = 0.f;
}

// ---------------------------------------------------------------------------
// Kernel 5: enc2 tiled GEMM: out[b,n] = relu(E[b,:451] . e2w[n,:451] + e2b[n])
// ---------------------------------------------------------------------------
__global__ __launch_bounds__(256) void k_enc2(const float* __restrict__ e2w,
                                              const float* __restrict__ e2b,
                                              float* __restrict__ out) {
    __shared__ __align__(16) float As[64][68];
    __shared__ __align__(16) float Bs[64][68];
    int b0 = blockIdx.x * 64, n0 = blockIdx.y * 64;
    int t = threadIdx.x;
    int m0 = (t >> 4) << 2, q0 = (t & 15) << 2;

    unsigned long long acc[4][2];
    #pragma unroll
    for (int a = 0; a < 4; a++)
        #pragma unroll
        for (int p = 0; p < 2; p++) acc[a][p] = 0ull;

    for (int kc = 0; kc < 512; kc += 64) {
        __syncthreads();
        for (int e = t; e < 64 * 64; e += 256) {
            int r = e >> 6, kk = e & 63;
            int k = kc + kk;
            As[kk][r] = (k < 451) ? e2w[(n0 + r) * 451 + k] : 0.f;
            Bs[kk][r] = (k < 451) ? g_E[(b0 + r) * 456 + k] : 0.f;
        }
        __syncthreads();
        #pragma unroll 16
        for (int kk = 0; kk < 64; ++kk) {
            float4 a4 = *(const float4*)&As[kk][m0];
            ulonglong2 bb = *(const ulonglong2*)&Bs[kk][q0];
            unsigned long long a0 = dup2(a4.x), a1 = dup2(a4.y),
                               a2 = dup2(a4.z), a3 = dup2(a4.w);
            fma2(acc[0][0], a0, bb.x); fma2(acc[0][1], a0, bb.y);
            fma2(acc[1][0], a1, bb.x); fma2(acc[1][1], a1, bb.y);
            fma2(acc[2][0], a2, bb.x); fma2(acc[2][1], a2, bb.y);
            fma2(acc[3][0], a3, bb.x); fma2(acc[3][1], a3, bb.y);
        }
    }

    #pragma unroll
    for (int mi = 0; mi < 4; ++mi) {
        int n = n0 + m0 + mi;
        float bias = e2b[n];
        #pragma unroll
        for (int p = 0; p < 2; ++p) {
            unsigned long long v = acc[mi][p];
            float lo = __uint_as_float((unsigned)v);
            float hi = __uint_as_float((unsigned)(v >> 32));
            out[(b0 + q0 + 2 * p)     * NOUT + n] = fmaxf(lo + bias, 0.f);
            out[(b0 + q0 + 2 * p + 1) * NOUT + n] = fmaxf(hi + bias, 0.f);
        }
    }
}

// ---------------------------------------------------------------------------
extern "C" void kernel_launch(void* const* d_in, const int* in_sizes, int n_in,
                              void* d_out, int out_size) {
    Ptrs P;
    for (int i = 0; i < 25; i++) P.p[i] = (const float*)d_in[i];

    cudaFuncSetAttribute(k_gemm_mma, cudaFuncAttributeMaxDynamicSharedMemorySize, SMEM_GEMM);

    k_branches<<<32, 256>>>(P);
    k_pair<<<512, 256>>>();
    k_gemm_mma<<<dim3(4, 2, ZSPLIT), 256, SMEM_GEMM>>>((const float*)d_in[21]);
    k_reduce<<<512, 256>>>((const float*)d_in[22]);
    k_enc2<<<dim3(8, 4), 256>>>((const float*)d_in[23], (const float*)d_in[24], (float*)d_out);
}

// round 7
// speedup vs baseline: 1.0017x; 1.0011x over previous
#include <cuda_runtime.h>
#include <cuda_bf16.h>
#include <math.h>
#include <stdint.h>

// Problem constants
#define BSZ   512
#define DD    64
#define DE    65
#define JK    4225      // 65*65
#define NOUT  256
#define KTOT  274625    // 65^3
#define ZSPLIT 18
#define NCH_TOT 8583    // ceil(274625/32)
#define CH_PER 477      // ceil(8583/18)

// Scratch (static device arrays only)
__device__ float g_oe[3 * BSZ * DE];            // o1e/o2e/o3e with appended 1.0
__device__ float g_P[BSZ * JK];                 // P[b][jk] = o2e[b][j]*o3e[b][k]
__device__ float g_part[ZSPLIT * BSZ * NOUT];   // split-K partials [z][b][o]
__device__ float g_E[BSZ * 456];                // enc2 input [relu(enc1)|skips|pad]

struct Ptrs { const float* p[25]; };

__device__ __forceinline__ unsigned long long dup2(float x) {
    unsigned long long r;
    asm("mov.b64 %0, {%1, %1};" : "=l"(r) : "r"(__float_as_uint(x)));
    return r;
}
__device__ __forceinline__ void fma2(unsigned long long& acc, unsigned long long a, unsigned long long b) {
    asm("fma.rn.f32x2 %0, %1, %2, %0;" : "+l"(acc) : "l"(a), "l"(b));
}

__device__ __forceinline__ void mma_bf16(float* d, const uint32_t* a, const uint32_t* b) {
    asm volatile("mma.sync.aligned.m16n8k16.row.col.f32.bf16.bf16.f32 "
        "{%0,%1,%2,%3}, {%4,%5,%6,%7}, {%8,%9}, {%0,%1,%2,%3};"
        : "+f"(d[0]), "+f"(d[1]), "+f"(d[2]), "+f"(d[3])
        : "r"(a[0]), "r"(a[1]), "r"(a[2]), "r"(a[3]), "r"(b[0]), "r"(b[1]));
}

// ---------------------------------------------------------------------------
// Kernel 1: three gated branches -> o1e/o2e/o3e [512][65] (last col = 1.0)
// ---------------------------------------------------------------------------
__global__ __launch_bounds__(256) void k_branches(Ptrs P) {
    __shared__ float vs[3][16][DD];
    __shared__ float gs[16][DD];
    int b0 = blockIdx.x * 16;
    int t = threadIdx.x;

    for (int e = t; e < 16 * DD; e += 256) {
        int bb = e >> 6, m = e & 63;
        vs[0][bb][m] = P.p[0][(b0 + bb) * DD + m];
        vs[1][bb][m] = P.p[1][(b0 + bb) * DD + m];
        vs[2][bb][m] = P.p[2][(b0 + bb) * DD + m];
    }
    __syncthreads();

    int o = t & 63, bg = t >> 6;
    for (int br = 0; br < 3; ++br) {
        const float* hw = P.p[3 + br * 6];
        const float* hb = P.p[4 + br * 6];
        const float* zw = P.p[5 + br * 6];
        const float* zb = P.p[6 + br * 6];
        const float* ow = P.p[7 + br * 6];
        const float* ob = P.p[8 + br * 6];
        int hv = br;
        int x1 = (br == 1) ? 1 : 0;

        float hacc[4], zacc[4];
        #pragma unroll
        for (int q = 0; q < 4; q++) { hacc[q] = hb[o]; zacc[q] = zb[o]; }

        const float* hwr = hw + o * DD;
        #pragma unroll 8
        for (int m = 0; m < DD; m++) {
            float w = hwr[m];
            #pragma unroll
            for (int q = 0; q < 4; q++) hacc[q] += w * vs[hv][bg * 4 + q][m];
        }

        for (int i = 0; i < DD; i++) {
            float s[4] = {0.f, 0.f, 0.f, 0.f};
            const float* zr = zw + o * DD * DD + i * DD;
            #pragma unroll 8
            for (int j = 0; j < DD; j++) {
                float w = zr[j];
                #pragma unroll
                for (int q = 0; q < 4; q++) s[q] += w * vs[2][bg * 4 + q][j];
            }
            #pragma unroll
            for (int q = 0; q < 4; q++) zacc[q] += vs[x1][bg * 4 + q][i] * s[q];
        }

        #pragma unroll
        for (int q = 0; q < 4; q++) {
            float h = fmaxf(hacc[q], 0.f);
            float sg = 1.f / (1.f + expf(-zacc[q]));
            gs[bg * 4 + q][o] = h * sg;
        }
        __syncthreads();

        float oacc[4];
        #pragma unroll
        for (int q = 0; q < 4; q++) oacc[q] = ob[o];
        const float* owr = ow + o * DD;
        #pragma unroll 8
        for (int m = 0; m < DD; m++) {
            float w = owr[m];
            #pragma unroll
            for (int q = 0; q < 4; q++) oacc[q] += w * gs[bg * 4 + q][m];
        }
        #pragma unroll
        for (int q = 0; q < 4; q++) {
            g_oe[((long long)br * BSZ + b0 + bg * 4 + q) * DE + o] = fmaxf(oacc[q], 0.f);
            if (o == 0) g_oe[((long long)br * BSZ + b0 + bg * 4 + q) * DE + DD] = 1.f;
        }
        __syncthreads();
    }
}

// ---------------------------------------------------------------------------
// Kernel 2: P[b][j*65+k] = o2e[b][j] * o3e[b][k]
// ---------------------------------------------------------------------------
__global__ __launch_bounds__(256) void k_pair() {
    int b = blockIdx.x, t = threadIdx.x;
    __shared__ float s2[DE], s3[DE];
    if (t < DE)           s2[t]      = g_oe[(1 * BSZ + b) * DE + t];
    else if (t < 2 * DE)  s3[t - DE] = g_oe[(2 * BSZ + b) * DE + (t - DE)];
    __syncthreads();
    for (int e = t; e < JK; e += 256) {
        int j = e / DE, k = e - j * DE;
        g_P[b * JK + e] = s2[j] * s3[k];
    }
}

// ---------------------------------------------------------------------------
// Kernel 3: big GEMM via mma.sync bf16 3-pass (base-PTX tensor path).
// C[o 256, b 512] = sum_kb W[o,kb] * Bmat[kb,b], Bmat = o1e[b,i]*P[b,jk].
// CTA tile 128(o) x 128(b), chunk = 32 k, grid (4 btiles, 2 otiles, 18 splits).
// ---------------------------------------------------------------------------
#define SROW     80                 // bytes per smem row (40 bf16, conflict-free pad)
#define O1_BYTES (128 * 66 * 4)     // 33792
#define STAGE_SZ 40960              // 4 planes * 128 rows * 80 B
#define AH_OFF   0
#define AL_OFF   10240
#define BH_OFF   20480
#define BL_OFF   30720
#define SMEM_GEMM (O1_BYTES + 2 * STAGE_SZ)

__global__ __launch_bounds__(256, 1) void k_gemm_mma(const float* __restrict__ W) {
    extern __shared__ char smem[];
    float* o1s = (float*)smem;                       // [128][66]
    const int t = threadIdx.x, w = t >> 5, lane = t & 31;
    const int gid = lane >> 2, tig = lane & 3;
    const int warp_m = w >> 2, warp_n = w & 3;
    const int b0 = blockIdx.x * 128, o0 = blockIdx.y * 128, z = blockIdx.z;

    // cache o1e for this CTA's b-range
    for (int e = t; e < 128 * DE; e += 256) {
        int bl = e / DE, ii = e - bl * DE;
        o1s[bl * 66 + ii] = g_oe[(b0 + bl) * DE + ii];
    }
    __syncthreads();

    const int c0 = z * CH_PER;
    const int nch = min(c0 + CH_PER, NCH_TOT) - c0;

    float acc[4][4][4];
    #pragma unroll
    for (int mt = 0; mt < 4; mt++)
        #pragma unroll
        for (int nt = 0; nt < 4; nt++)
            #pragma unroll
            for (int q = 0; q < 4; q++) acc[mt][nt][q] = 0.f;

    float aR[16], bR[16];

    // prefetch chunk c0
    {
        int kb = c0 * 32 + lane;
        bool ok = kb < KTOT;
        int kk = ok ? kb : 0;
        int i = kk / JK, jk = kk - i * JK;
        const float* wp = W + (size_t)(o0 + w * 16) * KTOT + kk;
        const float* pp = g_P + (size_t)(b0 + w * 16) * JK + jk;
        #pragma unroll
        for (int r = 0; r < 16; r++) {
            aR[r] = ok ? __ldg(wp + (size_t)r * KTOT) : 0.f;
            bR[r] = ok ? __ldg(pp + (size_t)r * JK) : 0.f;
        }
    }

    for (int ci = 0; ci < nch; ++ci) {
        const int s = ci & 1;
        char* st = smem + O1_BYTES + s * STAGE_SZ;

        // store prefetched chunk to smem as bf16 hi/lo planes
        {
            int kb = (c0 + ci) * 32 + lane;
            int kk = (kb < KTOT) ? kb : 0;
            int i = kk / JK;
            uint32_t off = (uint32_t)(w * 16) * SROW + lane * 2;
            #pragma unroll
            for (int r = 0; r < 16; r++) {
                float v = aR[r];
                __nv_bfloat16 h = __float2bfloat16(v);
                __nv_bfloat16 l = __float2bfloat16(v - __bfloat162float(h));
                *(__nv_bfloat16*)(st + AH_OFF + off + r * SROW) = h;
                *(__nv_bfloat16*)(st + AL_OFF + off + r * SROW) = l;
                float u = bR[r] * o1s[(w * 16 + r) * 66 + i];
                __nv_bfloat16 h2 = __float2bfloat16(u);
                __nv_bfloat16 l2 = __float2bfloat16(u - __bfloat162float(h2));
                *(__nv_bfloat16*)(st + BH_OFF + off + r * SROW) = h2;
                *(__nv_bfloat16*)(st + BL_OFF + off + r * SROW) = l2;
            }
        }
        __syncthreads();

        // prefetch next chunk (hidden under mma below)
        if (ci + 1 < nch) {
            int kb = (c0 + ci + 1) * 32 + lane;
            bool ok = kb < KTOT;
            int kk = ok ? kb : 0;
            int i = kk / JK, jk = kk - i * JK;
            const float* wp = W + (size_t)(o0 + w * 16) * KTOT + kk;
            const float* pp = g_P + (size_t)(b0 + w * 16) * JK + jk;
            #pragma unroll
            for (int r = 0; r < 16; r++) {
                aR[r] = ok ? __ldg(wp + (size_t)r * KTOT) : 0.f;
                bR[r] = ok ? __ldg(pp + (size_t)r * JK) : 0.f;
            }
        }

        // compute on stage s
        {
            const char* sc = smem + O1_BYTES + s * STAGE_SZ;
            #pragma unroll
            for (int kh = 0; kh < 2; ++kh) {
                uint32_t ah[4][4], al[4][4], bh[4][2], bl[4][2];
                #pragma unroll
                for (int mt = 0; mt < 4; mt++) {
                    uint32_t r0 = (uint32_t)(warp_m * 64 + mt * 16 + gid) * SROW + tig * 4 + kh * 32;
                    ah[mt][0] = *(const uint32_t*)(sc + AH_OFF + r0);
                    ah[mt][1] = *(const uint32_t*)(sc + AH_OFF + r0 + 8 * SROW);
                    ah[mt][2] = *(const uint32_t*)(sc + AH_OFF + r0 + 16);
                    ah[mt][3] = *(const uint32_t*)(sc + AH_OFF + r0 + 8 * SROW + 16);
                    al[mt][0] = *(const uint32_t*)(sc + AL_OFF + r0);
                    al[mt][1] = *(const uint32_t*)(sc + AL_OFF + r0 + 8 * SROW);
                    al[mt][2] = *(const uint32_t*)(sc + AL_OFF + r0 + 16);
                    al[mt][3] = *(const uint32_t*)(sc + AL_OFF + r0 + 8 * SROW + 16);
                }
                #pragma unroll
                for (int nt = 0; nt < 4; nt++) {
                    uint32_t r0 = (uint32_t)(warp_n * 32 + nt * 8 + gid) * SROW + tig * 4 + kh * 32;
                    bh[nt][0] = *(const uint32_t*)(sc + BH_OFF + r0);
                    bh[nt][1] = *(const uint32_t*)(sc + BH_OFF + r0 + 16);
                    bl[nt][0] = *(const uint32_t*)(sc + BL_OFF + r0);
                    bl[nt][1] = *(const uint32_t*)(sc + BL_OFF + r0 + 16);
                }
                #pragma unroll
                for (int mt = 0; mt < 4; mt++)
                    #pragma unroll
                    for (int nt = 0; nt < 4; nt++)
                        mma_bf16(acc[mt][nt], ah[mt], bh[nt]);
                #pragma unroll
                for (int mt = 0; mt < 4; mt++)
                    #pragma unroll
                    for (int nt = 0; nt < 4; nt++)
                        mma_bf16(acc[mt][nt], al[mt], bh[nt]);
                #pragma unroll
                for (int mt = 0; mt < 4; mt++)
                    #pragma unroll
                    for (int nt = 0; nt < 4; nt++)
                        mma_bf16(acc[mt][nt], ah[mt], bl[nt]);
            }
        }
    }

    // epilogue: acc -> g_part[z][b][o]
    float* gp = g_part + (size_t)z * BSZ * NOUT;
    #pragma unroll
    for (int mt = 0; mt < 4; mt++) {
        int o = o0 + warp_m * 64 + mt * 16 + gid;
        #pragma unroll
        for (int nt = 0; nt < 4; nt++) {
            int b = b0 + warp_n * 32 + nt * 8 + tig * 2;
            gp[(size_t)b * NOUT + o]           = acc[mt][nt][0];
            gp[(size_t)(b + 1) * NOUT + o]     = acc[mt][nt][1];
            gp[(size_t)b * NOUT + o + 8]       = acc[mt][nt][2];
            gp[(size_t)(b + 1) * NOUT + o + 8] = acc[mt][nt][3];
        }
    }
}

// ---------------------------------------------------------------------------
// Kernel 4: reduce split-K partials + enc1 bias/relu + build enc2 input
// ---------------------------------------------------------------------------
__global__ __launch_bounds__(256) void k_reduce(const float* __restrict__ e1b) {
    int b = blockIdx.x, t = threadIdx.x;
    float s = e1b[t];
    #pragma unroll 6
    for (int zz = 0; zz < ZSPLIT; ++zz)
        s += g_part[((size_t)zz * BSZ + b) * NOUT + t];
    g_E[b * 456 + t] = fmaxf(s, 0.f);
    if (t < 195)
        g_E[b * 456 + 256 + t] = g_oe[((t / 65) * BSZ + b) * DE + (t % 65)];
    else if (t < 200)
        g_E[b * 456 + 451 + (t - 195)] = 0.f;
}

// ---------------------------------------------------------------------------
// Kernel 5: enc2 tiled GEMM: out[b,n] = relu(E[b,:451] . e2w[n,:451] + e2b[n])
// ---------------------------------------------------------------------------
__global__ __launch_bounds__(256) void k_enc2(const float* __restrict__ e2w,
                                              const float* __restrict__ e2b,
                                              float* __restrict__ out) {
    __shared__ __align__(16) float As[64][68];
    __shared__ __align__(16) float Bs[64][68];
    int b0 = blockIdx.x * 64, n0 = blockIdx.y * 64;
    int t = threadIdx.x;
    int m0 = (t >> 4) << 2, q0 = (t & 15) << 2;

    unsigned long long acc[4][2];
    #pragma unroll
    for (int a = 0; a < 4; a++)
        #pragma unroll
        for (int p = 0; p < 2; p++) acc[a][p] = 0ull;

    for (int kc = 0; kc < 512; kc += 64) {
        __syncthreads();
        for (int e = t; e < 64 * 64; e += 256) {
            int r = e >> 6, kk = e & 63;
            int k = kc + kk;
            As[kk][r] = (k < 451) ? e2w[(n0 + r) * 451 + k] : 0.f;
            Bs[kk][r] = (k < 451) ? g_E[(b0 + r) * 456 + k] : 0.f;
        }
        __syncthreads();
        #pragma unroll 16
        for (int kk = 0; kk < 64; ++kk) {
            float4 a4 = *(const float4*)&As[kk][m0];
            ulonglong2 bb = *(const ulonglong2*)&Bs[kk][q0];
            unsigned long long a0 = dup2(a4.x), a1 = dup2(a4.y),
                               a2 = dup2(a4.z), a3 = dup2(a4.w);
            fma2(acc[0][0], a0, bb.x); fma2(acc[0][1], a0, bb.y);
            fma2(acc[1][0], a1, bb.x); fma2(acc[1][1], a1, bb.y);
            fma2(acc[2][0], a2, bb.x); fma2(acc[2][1], a2, bb.y);
            fma2(acc[3][0], a3, bb.x); fma2(acc[3][1], a3, bb.y);
        }
    }

    #pragma unroll
    for (int mi = 0; mi < 4; ++mi) {
        int n = n0 + m0 + mi;
        float bias = e2b[n];
        #pragma unroll
        for (int p = 0; p < 2; ++p) {
            unsigned long long v = acc[mi][p];
            float lo = __uint_as_float((unsigned)v);
            float hi = __uint_as_float((unsigned)(v >> 32));
            out[(b0 + q0 + 2 * p)     * NOUT + n] = fmaxf(lo + bias, 0.f);
            out[(b0 + q0 + 2 * p + 1) * NOUT + n] = fmaxf(hi + bias, 0.f);
        }
    }
}

// ---------------------------------------------------------------------------
extern "C" void kernel_launch(void* const* d_in, const int* in_sizes, int n_in,
                              void* d_out, int out_size) {
    Ptrs P;
    for (int i = 0; i < 25; i++) P.p[i] = (const float*)d_in[i];

    cudaFuncSetAttribute(k_gemm_mma, cudaFuncAttributeMaxDynamicSharedMemorySize, SMEM_GEMM);

    k_branches<<<32, 256>>>(P);
    k_pair<<<512, 256>>>();
    k_gemm_mma<<<dim3(4, 2, ZSPLIT), 256, SMEM_GEMM>>>((const float*)d_in[21]);
    k_reduce<<<512, 256>>>((const float*)d_in[22]);
    k_enc2<<<dim3(8, 4), 256>>>((const float*)d_in[23], (const float*)d_in[24], (float*)d_out);
}

// round 8
// speedup vs baseline: 2.0539x; 2.0504x over previous
#include <cuda_runtime.h>
#include <cuda_fp16.h>
#include <math.h>
#include <stdint.h>

// Problem constants
#define BSZ   512
#define DD    64
#define DE    65
#define JK    4225      // 65*65
#define NOUT  256
#define KTOT  274625    // 65^3
#define KPAD  274688    // KTOT padded to multiple of 32 (and 16B rows)
#define NCH_TOT 8584    // KPAD/32
#define ZSPLIT 18
#define CH_PER 477      // ceil(8584/18)

#define WSCALE   1024.0f
#define WSCALE_INV (1.0f/1024.0f)

// Scratch (static device arrays only)
__device__ float g_oe[3 * BSZ * DE];            // o1e/o2e/o3e with appended 1.0
__device__ float g_part[ZSPLIT * BSZ * NOUT];   // split-K partials [z][b][o]
__device__ float g_E[BSZ * 456];                // enc2 input
__device__ __align__(128) __half g_Wh[(size_t)NOUT * KPAD];  // W*1024 hi plane
__device__ __align__(128) __half g_Wl[(size_t)NOUT * KPAD];  // W*1024 lo plane
__device__ __align__(128) __half g_Bp[(size_t)BSZ * KPAD];   // B = o1*o2*o3 fp16

struct Ptrs { const float* p[25]; };

__device__ __forceinline__ uint32_t smem_u32(const void* p) {
    uint32_t a;
    asm("{ .reg .u64 t; cvta.to.shared.u64 t, %1; cvt.u32.u64 %0, t; }" : "=r"(a) : "l"(p));
    return a;
}
__device__ __forceinline__ void cp_async16(uint32_t dst, const void* src) {
    asm volatile("cp.async.cg.shared.global [%0], [%1], 16;" :: "r"(dst), "l"(src) : "memory");
}
__device__ __forceinline__ void mma_f16(float* d, const uint32_t* a, const uint32_t* b) {
    asm volatile("mma.sync.aligned.m16n8k16.row.col.f32.f16.f16.f32 "
        "{%0,%1,%2,%3}, {%4,%5,%6,%7}, {%8,%9}, {%0,%1,%2,%3};"
        : "+f"(d[0]), "+f"(d[1]), "+f"(d[2]), "+f"(d[3])
        : "r"(a[0]), "r"(a[1]), "r"(a[2]), "r"(a[3]), "r"(b[0]), "r"(b[1]));
}
__device__ __forceinline__ unsigned long long dup2(float x) {
    unsigned long long r;
    asm("mov.b64 %0, {%1, %1};" : "=l"(r) : "r"(__float_as_uint(x)));
    return r;
}
__device__ __forceinline__ void fma2(unsigned long long& acc, unsigned long long a, unsigned long long b) {
    asm("fma.rn.f32x2 %0, %1, %2, %0;" : "+l"(acc) : "l"(a), "l"(b));
}

// ---------------------------------------------------------------------------
// Kernel A: prep W -> fp16 hi/lo planes (scaled by 1024), padded/zeroed
// ---------------------------------------------------------------------------
__global__ __launch_bounds__(256) void k_prepW(const float* __restrict__ W) {
    int row = blockIdx.y;
    int k = (blockIdx.x * 256 + threadIdx.x) * 2;
    if (k >= KPAD) return;
    float w0 = (k     < KTOT) ? W[(size_t)row * KTOT + k]     * WSCALE : 0.f;
    float w1 = (k + 1 < KTOT) ? W[(size_t)row * KTOT + k + 1] * WSCALE : 0.f;
    __half h0 = __float2half_rn(w0), h1 = __float2half_rn(w1);
    __half l0 = __float2half_rn(w0 - __half2float(h0));
    __half l1 = __float2half_rn(w1 - __half2float(h1));
    size_t o = (size_t)row * KPAD + k;
    *(__half2*)&g_Wh[o] = __halves2half2(h0, h1);
    *(__half2*)&g_Wl[o] = __halves2half2(l0, l1);
}

// ---------------------------------------------------------------------------
// Kernel 1: gated branches (branch = blockIdx.y) -> o1e/o2e/o3e [512][65]
// ---------------------------------------------------------------------------
__global__ __launch_bounds__(256) void k_branches(Ptrs P) {
    __shared__ float vs[3][16][DD];
    __shared__ float gs[16][DD];
    int b0 = blockIdx.x * 16;
    int br = blockIdx.y;
    int t = threadIdx.x;

    for (int e = t; e < 16 * DD; e += 256) {
        int bb = e >> 6, m = e & 63;
        vs[0][bb][m] = P.p[0][(b0 + bb) * DD + m];
        vs[1][bb][m] = P.p[1][(b0 + bb) * DD + m];
        vs[2][bb][m] = P.p[2][(b0 + bb) * DD + m];
    }
    __syncthreads();

    int o = t & 63, bg = t >> 6;
    const float* hw = P.p[3 + br * 6];
    const float* hb = P.p[4 + br * 6];
    const float* zw = P.p[5 + br * 6];
    const float* zb = P.p[6 + br * 6];
    const float* ow = P.p[7 + br * 6];
    const float* ob = P.p[8 + br * 6];
    int hv = br;
    int x1 = (br == 1) ? 1 : 0;

    float hacc[4], zacc[4];
    #pragma unroll
    for (int q = 0; q < 4; q++) { hacc[q] = hb[o]; zacc[q] = zb[o]; }

    const float* hwr = hw + o * DD;
    #pragma unroll 8
    for (int m = 0; m < DD; m++) {
        float w = hwr[m];
        #pragma unroll
        for (int q = 0; q < 4; q++) hacc[q] += w * vs[hv][bg * 4 + q][m];
    }

    for (int i = 0; i < DD; i++) {
        float s[4] = {0.f, 0.f, 0.f, 0.f};
        const float* zr = zw + o * DD * DD + i * DD;
        #pragma unroll 8
        for (int j = 0; j < DD; j++) {
            float w = zr[j];
            #pragma unroll
            for (int q = 0; q < 4; q++) s[q] += w * vs[2][bg * 4 + q][j];
        }
        #pragma unroll
        for (int q = 0; q < 4; q++) zacc[q] += vs[x1][bg * 4 + q][i] * s[q];
    }

    #pragma unroll
    for (int q = 0; q < 4; q++) {
        float h = fmaxf(hacc[q], 0.f);
        float sg = 1.f / (1.f + expf(-zacc[q]));
        gs[bg * 4 + q][o] = h * sg;
    }
    __syncthreads();

    float oacc[4];
    #pragma unroll
    for (int q = 0; q < 4; q++) oacc[q] = ob[o];
    const float* owr = ow + o * DD;
    #pragma unroll 8
    for (int m = 0; m < DD; m++) {
        float w = owr[m];
        #pragma unroll
        for (int q = 0; q < 4; q++) oacc[q] += w * gs[bg * 4 + q][m];
    }
    #pragma unroll
    for (int q = 0; q < 4; q++) {
        g_oe[((long long)br * BSZ + b0 + bg * 4 + q) * DE + o] = fmaxf(oacc[q], 0.f);
        if (o == 0) g_oe[((long long)br * BSZ + b0 + bg * 4 + q) * DE + DD] = 1.f;
    }
}

// ---------------------------------------------------------------------------
// Kernel 2: prep B plane fp16: Bp[b][i*4225+jk] = o1e[b,i]*o2e[b,j]*o3e[b,k]
// grid (512, 66): i==65 writes the 63-element zero pad.
// ---------------------------------------------------------------------------
__global__ __launch_bounds__(256) void k_prepB() {
    int b = blockIdx.x, i = blockIdx.y, t = threadIdx.x;
    if (i == 65) {
        if (t < KPAD - KTOT) g_Bp[(size_t)b * KPAD + KTOT + t] = __float2half_rn(0.f);
        return;
    }
    __shared__ float s2[DE], s3[DE];
    if (t < DE)           s2[t]      = g_oe[(1 * BSZ + b) * DE + t];
    else if (t < 2 * DE)  s3[t - DE] = g_oe[(2 * BSZ + b) * DE + (t - DE)];
    __syncthreads();
    float o1 = g_oe[(0 * BSZ + b) * DE + i];
    size_t base = (size_t)b * KPAD + (size_t)i * JK;
    for (int e = t; e < JK; e += 256) {
        int j = e / DE, k = e - j * DE;
        g_Bp[base + e] = __float2half_rn(o1 * s2[j] * s3[k]);
    }
}

// ---------------------------------------------------------------------------
// Kernel 3: GEMM via mma.sync fp16 2-pass, pure cp.async 4-stage pipeline.
// C[o 256, b 512] = sum_k (Wh+Wl)[o,k] * Bp[k,b]   (result scaled by 1024)
// CTA 128o x 128b, chunk = 32 k, grid (4 btiles, 2 otiles, 18 zsplits).
// ---------------------------------------------------------------------------
#define SROW   80        // smem row stride (64B data + pad) -> conflict-free
#define PL_SZ  10240     // 128 rows * 80B
#define AH_OFF 0
#define AL_OFF 10240
#define BH_OFF 20480
#define STAGE  30720
#define NST    4
#define SMEM_GEMM (NST * STAGE)   // 122880

__global__ __launch_bounds__(256, 1) void k_gemm_mma() {
    extern __shared__ char smem[];
    const uint32_t sb = smem_u32(smem);
    const int t = threadIdx.x, w = t >> 5, lane = t & 31;
    const int gid = lane >> 2, tig = lane & 3;
    const int warp_m = w >> 2, warp_n = w & 3;
    const int b0 = blockIdx.x * 128, o0 = blockIdx.y * 128, z = blockIdx.z;
    const int c0 = z * CH_PER;
    const int nch = min(c0 + CH_PER, NCH_TOT) - c0;

    // per-thread cp.async descriptors: 1536 16B-transfers / 256 threads = 6
    const __half* srcb[6];
    uint32_t dsto[6];
    #pragma unroll
    for (int q = 0; q < 6; q++) {
        int e = t + 256 * q;
        int plane = e >> 9;           // 0=Ah, 1=Al, 2=Bh
        int idx = e & 511;
        int r = idx >> 2, qd = idx & 3;
        const __half* base = (plane == 0) ? g_Wh : (plane == 1) ? g_Wl : g_Bp;
        int row = (plane == 2) ? (b0 + r) : (o0 + r);
        srcb[q] = base + (size_t)row * KPAD + qd * 8;
        dsto[q] = (uint32_t)(plane * PL_SZ + r * SROW + qd * 16);
    }

    float acc[4][4][4];
    #pragma unroll
    for (int mt = 0; mt < 4; mt++)
        #pragma unroll
        for (int nt = 0; nt < 4; nt++)
            #pragma unroll
            for (int q = 0; q < 4; q++) acc[mt][nt][q] = 0.f;

    // prologue: fill stages 0..NST-2
    #pragma unroll
    for (int p = 0; p < NST - 1; ++p) {
        if (p < nch) {
            int kb0 = (c0 + p) * 32;
            uint32_t stb = sb + (uint32_t)(p % NST) * STAGE;
            #pragma unroll
            for (int q = 0; q < 6; q++) cp_async16(stb + dsto[q], srcb[q] + kb0);
        }
        asm volatile("cp.async.commit_group;" ::: "memory");
    }

    for (int ci = 0; ci < nch; ++ci) {
        // issue fill for ci+NST-1 (stage was last used at ci-1; end-of-iter sync protects)
        {
            int cf = ci + NST - 1;
            if (cf < nch) {
                int kb0 = (c0 + cf) * 32;
                uint32_t stb = sb + (uint32_t)(cf % NST) * STAGE;
                #pragma unroll
                for (int q = 0; q < 6; q++) cp_async16(stb + dsto[q], srcb[q] + kb0);
            }
            asm volatile("cp.async.commit_group;" ::: "memory");
        }
        asm volatile("cp.async.wait_group %0;" :: "n"(NST - 2) : "memory");
        __syncthreads();

        const char* sc = smem + (size_t)(ci % NST) * STAGE;
        #pragma unroll
        for (int kh = 0; kh < 2; ++kh) {
            uint32_t ah[4][4], al[4][4], bh[4][2];
            #pragma unroll
            for (int mt = 0; mt < 4; mt++) {
                uint32_t r0 = (uint32_t)(warp_m * 64 + mt * 16 + gid) * SROW + tig * 4 + kh * 32;
                ah[mt][0] = *(const uint32_t*)(sc + AH_OFF + r0);
                ah[mt][1] = *(const uint32_t*)(sc + AH_OFF + r0 + 8 * SROW);
                ah[mt][2] = *(const uint32_t*)(sc + AH_OFF + r0 + 16);
                ah[mt][3] = *(const uint32_t*)(sc + AH_OFF + r0 + 8 * SROW + 16);
                al[mt][0] = *(const uint32_t*)(sc + AL_OFF + r0);
                al[mt][1] = *(const uint32_t*)(sc + AL_OFF + r0 + 8 * SROW);
                al[mt][2] = *(const uint32_t*)(sc + AL_OFF + r0 + 16);
                al[mt][3] = *(const uint32_t*)(sc + AL_OFF + r0 + 8 * SROW + 16);
            }
            #pragma unroll
            for (int nt = 0; nt < 4; nt++) {
                uint32_t r0 = (uint32_t)(warp_n * 32 + nt * 8 + gid) * SROW + tig * 4 + kh * 32;
                bh[nt][0] = *(const uint32_t*)(sc + BH_OFF + r0);
                bh[nt][1] = *(const uint32_t*)(sc + BH_OFF + r0 + 16);
            }
            #pragma unroll
            for (int mt = 0; mt < 4; mt++)
                #pragma unroll
                for (int nt = 0; nt < 4; nt++)
                    mma_f16(acc[mt][nt], ah[mt], bh[nt]);
            #pragma unroll
            for (int mt = 0; mt < 4; mt++)
                #pragma unroll
                for (int nt = 0; nt < 4; nt++)
                    mma_f16(acc[mt][nt], al[mt], bh[nt]);
        }
        __syncthreads();
    }

    // epilogue: acc -> g_part[z][b][o]   (values carry the 1024x W scale)
    float* gp = g_part + (size_t)z * BSZ * NOUT;
    #pragma unroll
    for (int mt = 0; mt < 4; mt++) {
        int o = o0 + warp_m * 64 + mt * 16 + gid;
        #pragma unroll
        for (int nt = 0; nt < 4; nt++) {
            int b = b0 + warp_n * 32 + nt * 8 + tig * 2;
            gp[(size_t)b * NOUT + o]           = acc[mt][nt][0];
            gp[(size_t)(b + 1) * NOUT + o]     = acc[mt][nt][1];
            gp[(size_t)b * NOUT + o + 8]       = acc[mt][nt][2];
            gp[(size_t)(b + 1) * NOUT + o + 8] = acc[mt][nt][3];
        }
    }
}

// ---------------------------------------------------------------------------
// Kernel 4: reduce split-K partials (undo 1024x) + bias/relu + enc2 input
// ---------------------------------------------------------------------------
__global__ __launch_bounds__(256) void k_reduce(const float* __restrict__ e1b) {
    int b = blockIdx.x, t = threadIdx.x;
    float s = 0.f;
    #pragma unroll 6
    for (int zz = 0; zz < ZSPLIT; ++zz)
        s += g_part[((size_t)zz * BSZ + b) * NOUT + t];
    s = e1b[t] + s * WSCALE_INV;
    g_E[b * 456 + t] = fmaxf(s, 0.f);
    if (t < 195)
        g_E[b * 456 + 256 + t] = g_oe[((t / 65) * BSZ + b) * DE + (t % 65)];
    else if (t < 200)
        g_E[b * 456 + 451 + (t - 195)] = 0.f;
}

// ---------------------------------------------------------------------------
// Kernel 5: enc2 tiled GEMM: out[b,n] = relu(E[b,:451] . e2w[n,:451] + e2b[n])
// ---------------------------------------------------------------------------
__global__ __launch_bounds__(256) void k_enc2(const float* __restrict__ e2w,
                                              const float* __restrict__ e2b,
                                              float* __restrict__ out) {
    __shared__ __align__(16) float As[64][68];
    __shared__ __align__(16) float Bs[64][68];
    int b0 = blockIdx.x * 64, n0 = blockIdx.y * 64;
    int t = threadIdx.x;
    int m0 = (t >> 4) << 2, q0 = (t & 15) << 2;

    unsigned long long acc[4][2];
    #pragma unroll
    for (int a = 0; a < 4; a++)
        #pragma unroll
        for (int p = 0; p < 2; p++) acc[a][p] = 0ull;

    for (int kc = 0; kc < 512; kc += 64) {
        __syncthreads();
        for (int e = t; e < 64 * 64; e += 256) {
            int r = e >> 6, kk = e & 63;
            int k = kc + kk;
            As[kk][r] = (k < 451) ? e2w[(n0 + r) * 451 + k] : 0.f;
            Bs[kk][r] = (k < 451) ? g_E[(b0 + r) * 456 + k] : 0.f;
        }
        __syncthreads();
        #pragma unroll 16
        for (int kk = 0; kk < 64; ++kk) {
            float4 a4 = *(const float4*)&As[kk][m0];
            ulonglong2 bb = *(const ulonglong2*)&Bs[kk][q0];
            unsigned long long a0 = dup2(a4.x), a1 = dup2(a4.y),
                               a2 = dup2(a4.z), a3 = dup2(a4.w);
            fma2(acc[0][0], a0, bb.x); fma2(acc[0][1], a0, bb.y);
            fma2(acc[1][0], a1, bb.x); fma2(acc[1][1], a1, bb.y);
            fma2(acc[2][0], a2, bb.x); fma2(acc[2][1], a2, bb.y);
            fma2(acc[3][0], a3, bb.x); fma2(acc[3][1], a3, bb.y);
        }
    }

    #pragma unroll
    for (int mi = 0; mi < 4; ++mi) {
        int n = n0 + m0 + mi;
        float bias = e2b[n];
        #pragma unroll
        for (int p = 0; p < 2; ++p) {
            unsigned long long v = acc[mi][p];
            float lo = __uint_as_float((unsigned)v);
            float hi = __uint_as_float((unsigned)(v >> 32));
            out[(b0 + q0 + 2 * p)     * NOUT + n] = fmaxf(lo + bias, 0.f);
            out[(b0 + q0 + 2 * p + 1) * NOUT + n] = fmaxf(hi + bias, 0.f);
        }
    }
}

// ---------------------------------------------------------------------------
extern "C" void kernel_launch(void* const* d_in, const int* in_sizes, int n_in,
                              void* d_out, int out_size) {
    Ptrs P;
    for (int i = 0; i < 25; i++) P.p[i] = (const float*)d_in[i];

    cudaFuncSetAttribute(k_gemm_mma, cudaFuncAttributeMaxDynamicSharedMemorySize, SMEM_GEMM);

    k_prepW<<<dim3((KPAD / 2 + 255) / 256, 256), 256>>>((const float*)d_in[21]);
    k_branches<<<dim3(32, 3), 256>>>(P);
    k_prepB<<<dim3(512, 66), 256>>>();
    k_gemm_mma<<<dim3(4, 2, ZSPLIT), 256, SMEM_GEMM>>>();
    k_reduce<<<512, 256>>>((const float*)d_in[22]);
    k_enc2<<<dim3(8, 4), 256>>>((const float*)d_in[23], (const float*)d_in[24], (float*)d_out);
}

// round 9
// speedup vs baseline: 4.2236x; 2.0564x over previous
#include <cuda_runtime.h>
#include <cuda_fp16.h>
#include <math.h>
#include <stdint.h>

// Problem constants
#define BSZ   512
#define DD    64
#define DE    65
#define JK    4225      // 65*65
#define NOUT  256
#define KTOT  274625    // 65^3
#define KPAD  274688    // KTOT padded to multiple of 32
#define NCH_TOT 8584    // KPAD/32
#define ZSPLIT 18
#define CH_PER 477      // ceil(8584/18)

#define WSCALE   1024.0f
#define WSCALE_INV (1.0f/1024.0f)

// Scratch (static device arrays only)
__device__ float g_oe[3 * BSZ * DE];            // o1e/o2e/o3e with appended 1.0
__device__ float g_part[ZSPLIT * BSZ * NOUT];   // split-K partials [z][b][o]
__device__ float g_E[BSZ * 456];                // enc2 input
__device__ __align__(128) __half g_Wh[(size_t)NOUT * KPAD];  // W*1024 fp16
__device__ __align__(128) __half g_Bp[(size_t)BSZ * KPAD];   // B = o1*o2*o3 fp16

struct Ptrs { const float* p[25]; };

__device__ __forceinline__ uint32_t smem_u32(const void* p) {
    uint32_t a;
    asm("{ .reg .u64 t; cvta.to.shared.u64 t, %1; cvt.u32.u64 %0, t; }" : "=r"(a) : "l"(p));
    return a;
}
__device__ __forceinline__ void cp_async16(uint32_t dst, const void* src) {
    asm volatile("cp.async.cg.shared.global [%0], [%1], 16;" :: "r"(dst), "l"(src) : "memory");
}
__device__ __forceinline__ void mma_f16(float* d, const uint32_t* a, const uint32_t* b) {
    asm volatile("mma.sync.aligned.m16n8k16.row.col.f32.f16.f16.f32 "
        "{%0,%1,%2,%3}, {%4,%5,%6,%7}, {%8,%9}, {%0,%1,%2,%3};"
        : "+f"(d[0]), "+f"(d[1]), "+f"(d[2]), "+f"(d[3])
        : "r"(a[0]), "r"(a[1]), "r"(a[2]), "r"(a[3]), "r"(b[0]), "r"(b[1]));
}
__device__ __forceinline__ unsigned long long dup2(float x) {
    unsigned long long r;
    asm("mov.b64 %0, {%1, %1};" : "=l"(r) : "r"(__float_as_uint(x)));
    return r;
}
__device__ __forceinline__ void fma2(unsigned long long& acc, unsigned long long a, unsigned long long b) {
    asm("fma.rn.f32x2 %0, %1, %2, %0;" : "+l"(acc) : "l"(a), "l"(b));
}

// ---------------------------------------------------------------------------
// Kernel A: prep W -> single fp16 plane (scaled by 1024), padded/zeroed
// ---------------------------------------------------------------------------
__global__ __launch_bounds__(256) void k_prepW(const float* __restrict__ W) {
    int row = blockIdx.y;
    int k = (blockIdx.x * 256 + threadIdx.x) * 2;
    if (k >= KPAD) return;
    float w0 = (k     < KTOT) ? W[(size_t)row * KTOT + k]     * WSCALE : 0.f;
    float w1 = (k + 1 < KTOT) ? W[(size_t)row * KTOT + k + 1] * WSCALE : 0.f;
    *(__half2*)&g_Wh[(size_t)row * KPAD + k] =
        __halves2half2(__float2half_rn(w0), __float2half_rn(w1));
}

// ---------------------------------------------------------------------------
// Kernel 1: gated branches, SMEM-staged weights (coalesced zw slabs).
// grid (32 b-blocks, 3 branches), 256 threads: thread = (o 0..63, bg 0..3).
// ---------------------------------------------------------------------------
#define SMEM_BR ((3*16*64 + 2*64*65 + 64*65 + 16*64) * 4)   // 66304 B

__global__ __launch_bounds__(256) void k_branches(Ptrs P) {
    extern __shared__ float sm[];
    float* vs  = sm;               // [3][16][64]
    float* zsb = sm + 3072;        // [2][64][65]  slab [buf][j][o]
    float* ws  = zsb + 8320;       // [64][65]     staged hw / ow
    float* gsS = ws + 4160;        // [16][64]

    int b0 = blockIdx.x * 16;
    int br = blockIdx.y;
    int t = threadIdx.x;
    int o = t & 63, bg = t >> 6;

    const float* hw = P.p[3 + br * 6];
    const float* hb = P.p[4 + br * 6];
    const float* zw = P.p[5 + br * 6];
    const float* zb = P.p[6 + br * 6];
    const float* ow = P.p[7 + br * 6];
    const float* ob = P.p[8 + br * 6];
    int hv = br;
    int x1 = (br == 1) ? 1 : 0;

    // load input vectors + stage hw
    #pragma unroll
    for (int q = 0; q < 4; q++) {
        int e = t + 256 * q;
        int bb = e >> 6, m = e & 63;
        vs[(0 * 16 + bb) * 64 + m] = P.p[0][(b0 + bb) * DD + m];
        vs[(1 * 16 + bb) * 64 + m] = P.p[1][(b0 + bb) * DD + m];
        vs[(2 * 16 + bb) * 64 + m] = P.p[2][(b0 + bb) * DD + m];
    }
    #pragma unroll
    for (int q = 0; q < 16; q++) {
        int e = t + 256 * q;
        int r = e >> 6, m = e & 63;
        ws[r * 65 + m] = hw[r * 64 + m];
    }
    // preload zw slab 0: zs[0][j][oo] = zw[oo*4096 + j]  (coalesced in j)
    #pragma unroll
    for (int q = 0; q < 16; q++) {
        int e = t + 256 * q;
        int oo = e >> 6, j = e & 63;
        zsb[j * 65 + oo] = zw[oo * 4096 + j];
    }
    __syncthreads();

    // h = relu(hw @ v)
    float hacc[4];
    #pragma unroll
    for (int q = 0; q < 4; q++) hacc[q] = hb[o];
    #pragma unroll 8
    for (int m = 0; m < DD; m++) {
        float w = ws[o * 65 + m];
        #pragma unroll
        for (int q = 0; q < 4; q++) hacc[q] += w * vs[(hv * 16 + bg * 4 + q) * 64 + m];
    }

    // z bilinear: double-buffered slabs, LDG prefetch into regs over compute
    float zacc[4];
    #pragma unroll
    for (int q = 0; q < 4; q++) zacc[q] = zb[o];
    for (int i = 0; i < DD; i++) {
        float rt_[16];
        if (i + 1 < DD) {
            #pragma unroll
            for (int q = 0; q < 16; q++) {
                int e = t + 256 * q;
                int oo = e >> 6, j = e & 63;
                rt_[q] = zw[oo * 4096 + (i + 1) * 64 + j];
            }
        }
        const float* zc = zsb + (i & 1) * 4160;
        float s[4] = {0.f, 0.f, 0.f, 0.f};
        #pragma unroll 8
        for (int j = 0; j < DD; j++) {
            float zv = zc[j * 65 + o];
            #pragma unroll
            for (int q = 0; q < 4; q++) s[q] += zv * vs[(2 * 16 + bg * 4 + q) * 64 + j];
        }
        #pragma unroll
        for (int q = 0; q < 4; q++) zacc[q] += vs[(x1 * 16 + bg * 4 + q) * 64 + i] * s[q];
        if (i + 1 < DD) {
            float* zn = zsb + ((i + 1) & 1) * 4160;
            #pragma unroll
            for (int q = 0; q < 16; q++) {
                int e = t + 256 * q;
                int oo = e >> 6, j = e & 63;
                zn[j * 65 + oo] = rt_[q];
            }
        }
        __syncthreads();
    }

    // gate + stage ow
    #pragma unroll
    for (int q = 0; q < 16; q++) {
        int e = t + 256 * q;
        int r = e >> 6, m = e & 63;
        ws[r * 65 + m] = ow[r * 64 + m];
    }
    #pragma unroll
    for (int q = 0; q < 4; q++) {
        float h = fmaxf(hacc[q], 0.f);
        float sg = 1.f / (1.f + expf(-zacc[q]));
        gsS[(bg * 4 + q) * 64 + o] = h * sg;
    }
    __syncthreads();

    float oacc[4];
    #pragma unroll
    for (int q = 0; q < 4; q++) oacc[q] = ob[o];
    #pragma unroll 8
    for (int m = 0; m < DD; m++) {
        float w = ws[o * 65 + m];
        #pragma unroll
        for (int q = 0; q < 4; q++) oacc[q] += w * gsS[(bg * 4 + q) * 64 + m];
    }
    #pragma unroll
    for (int q = 0; q < 4; q++) {
        g_oe[((long long)br * BSZ + b0 + bg * 4 + q) * DE + o] = fmaxf(oacc[q], 0.f);
        if (o == 0) g_oe[((long long)br * BSZ + b0 + bg * 4 + q) * DE + DD] = 1.f;
    }
}

// ---------------------------------------------------------------------------
// Kernel 2: prep B plane fp16: Bp[b][i*4225+jk] = o1e[b,i]*o2e[b,j]*o3e[b,k]
// grid (512, 66): i==65 writes the 63-element zero pad.
// ---------------------------------------------------------------------------
__global__ __launch_bounds__(256) void k_prepB() {
    int b = blockIdx.x, i = blockIdx.y, t = threadIdx.x;
    if (i == 65) {
        if (t < KPAD - KTOT) g_Bp[(size_t)b * KPAD + KTOT + t] = __float2half_rn(0.f);
        return;
    }
    __shared__ float s2[DE], s3[DE];
    if (t < DE)           s2[t]      = g_oe[(1 * BSZ + b) * DE + t];
    else if (t < 2 * DE)  s3[t - DE] = g_oe[(2 * BSZ + b) * DE + (t - DE)];
    __syncthreads();
    float o1 = g_oe[(0 * BSZ + b) * DE + i];
    size_t base = (size_t)b * KPAD + (size_t)i * JK;
    bool aligned = ((i & 1) == 0);   // base parity = i parity
    for (int e = t * 2; e < JK - 1; e += 512) {
        int j0 = e / DE, k0 = e - j0 * DE;
        float v0 = o1 * s2[j0] * s3[k0];
        int j1 = j0, k1 = k0 + 1;
        if (k1 == DE) { j1++; k1 = 0; }
        float v1 = o1 * s2[j1] * s3[k1];
        __half h0 = __float2half_rn(v0), h1 = __float2half_rn(v1);
        if (aligned) *(__half2*)&g_Bp[base + e] = __halves2half2(h0, h1);
        else { g_Bp[base + e] = h0; g_Bp[base + e + 1] = h1; }
    }
    if (t == 0)  // last element (JK-1 = 4224): j=64,k=64
        g_Bp[base + JK - 1] = __float2half_rn(o1 * s2[DE - 1] * s3[DE - 1]);
}

// ---------------------------------------------------------------------------
// Kernel 3: GEMM via mma.sync fp16 single-pass, cp.async 5-stage pipeline.
// C[o 256, b 512] = sum_k Wh[o,k] * Bp[k,b]   (result scaled by 1024)
// CTA 128o x 128b, chunk = 32 k, grid (4 btiles, 2 otiles, 18 zsplits).
// ---------------------------------------------------------------------------
#define SROW   80        // smem row stride (64B data + pad) -> conflict-free
#define PL_SZ  10240     // 128 rows * 80B
#define AH_OFF 0
#define BH_OFF 10240
#define STAGE  20480
#define NST    5
#define SMEM_GEMM (NST * STAGE)   // 102400

__global__ __launch_bounds__(256, 1) void k_gemm_mma() {
    extern __shared__ char smem[];
    const uint32_t sb = smem_u32(smem);
    const int t = threadIdx.x, w = t >> 5, lane = t & 31;
    const int gid = lane >> 2, tig = lane & 3;
    const int warp_m = w >> 2, warp_n = w & 3;
    const int b0 = blockIdx.x * 128, o0 = blockIdx.y * 128, z = blockIdx.z;
    const int c0 = z * CH_PER;
    const int nch = min(c0 + CH_PER, NCH_TOT) - c0;

    // per-thread cp.async descriptors: 1024 16B-transfers / 256 threads = 4
    const __half* srcb[4];
    uint32_t dsto[4];
    #pragma unroll
    for (int q = 0; q < 4; q++) {
        int e = t + 256 * q;
        int plane = e >> 9;           // 0=A(W), 1=B
        int idx = e & 511;
        int r = idx >> 2, qd = idx & 3;
        const __half* base = plane ? g_Bp : g_Wh;
        int row = plane ? (b0 + r) : (o0 + r);
        srcb[q] = base + (size_t)row * KPAD + qd * 8;
        dsto[q] = (uint32_t)(plane * PL_SZ + r * SROW + qd * 16);
    }

    float acc[4][4][4];
    #pragma unroll
    for (int mt = 0; mt < 4; mt++)
        #pragma unroll
        for (int nt = 0; nt < 4; nt++)
            #pragma unroll
            for (int q = 0; q < 4; q++) acc[mt][nt][q] = 0.f;

    // prologue: fill stages 0..NST-2
    #pragma unroll
    for (int p = 0; p < NST - 1; ++p) {
        if (p < nch) {
            int kb0 = (c0 + p) * 32;
            uint32_t stb = sb + (uint32_t)(p % NST) * STAGE;
            #pragma unroll
            for (int q = 0; q < 4; q++) cp_async16(stb + dsto[q], srcb[q] + kb0);
        }
        asm volatile("cp.async.commit_group;" ::: "memory");
    }

    for (int ci = 0; ci < nch; ++ci) {
        {
            int cf = ci + NST - 1;
            if (cf < nch) {
                int kb0 = (c0 + cf) * 32;
                uint32_t stb = sb + (uint32_t)(cf % NST) * STAGE;
                #pragma unroll
                for (int q = 0; q < 4; q++) cp_async16(stb + dsto[q], srcb[q] + kb0);
            }
            asm volatile("cp.async.commit_group;" ::: "memory");
        }
        asm volatile("cp.async.wait_group %0;" :: "n"(NST - 2) : "memory");
        __syncthreads();

        const char* sc = smem + (size_t)(ci % NST) * STAGE;
        #pragma unroll
        for (int kh = 0; kh < 2; ++kh) {
            uint32_t ah[4][4], bh[4][2];
            #pragma unroll
            for (int mt = 0; mt < 4; mt++) {
                uint32_t r0 = (uint32_t)(warp_m * 64 + mt * 16 + gid) * SROW + tig * 4 + kh * 32;
                ah[mt][0] = *(const uint32_t*)(sc + AH_OFF + r0);
                ah[mt][1] = *(const uint32_t*)(sc + AH_OFF + r0 + 8 * SROW);
                ah[mt][2] = *(const uint32_t*)(sc + AH_OFF + r0 + 16);
                ah[mt][3] = *(const uint32_t*)(sc + AH_OFF + r0 + 8 * SROW + 16);
            }
            #pragma unroll
            for (int nt = 0; nt < 4; nt++) {
                uint32_t r0 = (uint32_t)(warp_n * 32 + nt * 8 + gid) * SROW + tig * 4 + kh * 32;
                bh[nt][0] = *(const uint32_t*)(sc + BH_OFF + r0);
                bh[nt][1] = *(const uint32_t*)(sc + BH_OFF + r0 + 16);
            }
            #pragma unroll
            for (int mt = 0; mt < 4; mt++)
                #pragma unroll
                for (int nt = 0; nt < 4; nt++)
                    mma_f16(acc[mt][nt], ah[mt], bh[nt]);
        }
        __syncthreads();
    }

    // epilogue: acc -> g_part[z][b][o]   (values carry the 1024x W scale)
    float* gp = g_part + (size_t)z * BSZ * NOUT;
    #pragma unroll
    for (int mt = 0; mt < 4; mt++) {
        int o = o0 + warp_m * 64 + mt * 16 + gid;
        #pragma unroll
        for (int nt = 0; nt < 4; nt++) {
            int b = b0 + warp_n * 32 + nt * 8 + tig * 2;
            gp[(size_t)b * NOUT + o]           = acc[mt][nt][0];
            gp[(size_t)(b + 1) * NOUT + o]     = acc[mt][nt][1];
            gp[(size_t)b * NOUT + o + 8]       = acc[mt][nt][2];
            gp[(size_t)(b + 1) * NOUT + o + 8] = acc[mt][nt][3];
        }
    }
}

// ---------------------------------------------------------------------------
// Kernel 4: reduce split-K partials (undo 1024x) + bias/relu + enc2 input
// ---------------------------------------------------------------------------
__global__ __launch_bounds__(256) void k_reduce(const float* __restrict__ e1b) {
    int b = blockIdx.x, t = threadIdx.x;
    float s = 0.f;
    #pragma unroll 6
    for (int zz = 0; zz < ZSPLIT; ++zz)
        s += g_part[((size_t)zz * BSZ + b) * NOUT + t];
    s = e1b[t] + s * WSCALE_INV;
    g_E[b * 456 + t] = fmaxf(s, 0.f);
    if (t < 195)
        g_E[b * 456 + 256 + t] = g_oe[((t / 65) * BSZ + b) * DE + (t % 65)];
    else if (t < 200)
        g_E[b * 456 + 451 + (t - 195)] = 0.f;
}

// ---------------------------------------------------------------------------
// Kernel 5: enc2 tiled GEMM: out[b,n] = relu(E[b,:451] . e2w[n,:451] + e2b[n])
// ---------------------------------------------------------------------------
__global__ __launch_bounds__(256) void k_enc2(const float* __restrict__ e2w,
                                              const float* __restrict__ e2b,
                                              float* __restrict__ out) {
    __shared__ __align__(16) float As[64][68];
    __shared__ __align__(16) float Bs[64][68];
    int b0 = blockIdx.x * 64, n0 = blockIdx.y * 64;
    int t = threadIdx.x;
    int m0 = (t >> 4) << 2, q0 = (t & 15) << 2;

    unsigned long long acc[4][2];
    #pragma unroll
    for (int a = 0; a < 4; a++)
        #pragma unroll
        for (int p = 0; p < 2; p++) acc[a][p] = 0ull;

    for (int kc = 0; kc < 512; kc += 64) {
        __syncthreads();
        for (int e = t; e < 64 * 64; e += 256) {
            int r = e >> 6, kk = e & 63;
            int k = kc + kk;
            As[kk][r] = (k < 451) ? e2w[(n0 + r) * 451 + k] : 0.f;
            Bs[kk][r] = (k < 451) ? g_E[(b0 + r) * 456 + k] : 0.f;
        }
        __syncthreads();
        #pragma unroll 16
        for (int kk = 0; kk < 64; ++kk) {
            float4 a4 = *(const float4*)&As[kk][m0];
            ulonglong2 bb = *(const ulonglong2*)&Bs[kk][q0];
            unsigned long long a0 = dup2(a4.x), a1 = dup2(a4.y),
                               a2 = dup2(a4.z), a3 = dup2(a4.w);
            fma2(acc[0][0], a0, bb.x); fma2(acc[0][1], a0, bb.y);
            fma2(acc[1][0], a1, bb.x); fma2(acc[1][1], a1, bb.y);
            fma2(acc[2][0], a2, bb.x); fma2(acc[2][1], a2, bb.y);
            fma2(acc[3][0], a3, bb.x); fma2(acc[3][1], a3, bb.y);
        }
    }

    #pragma unroll
    for (int mi = 0; mi < 4; ++mi) {
        int n = n0 + m0 + mi;
        float bias = e2b[n];
        #pragma unroll
        for (int p = 0; p < 2; ++p) {
            unsigned long long v = acc[mi][p];
            float lo = __uint_as_float((unsigned)v);
            float hi = __uint_as_float((unsigned)(v >> 32));
            out[(b0 + q0 + 2 * p)     * NOUT + n] = fmaxf(lo + bias, 0.f);
            out[(b0 + q0 + 2 * p + 1) * NOUT + n] = fmaxf(hi + bias, 0.f);
        }
    }
}

// ---------------------------------------------------------------------------
extern "C" void kernel_launch(void* const* d_in, const int* in_sizes, int n_in,
                              void* d_out, int out_size) {
    Ptrs P;
    for (int i = 0; i < 25; i++) P.p[i] = (const float*)d_in[i];

    cudaFuncSetAttribute(k_gemm_mma, cudaFuncAttributeMaxDynamicSharedMemorySize, SMEM_GEMM);
    cudaFuncSetAttribute(k_branches, cudaFuncAttributeMaxDynamicSharedMemorySize, SMEM_BR);

    k_prepW<<<dim3((KPAD / 2 + 255) / 256, 256), 256>>>((const float*)d_in[21]);
    k_branches<<<dim3(32, 3), 256, SMEM_BR>>>(P);
    k_prepB<<<dim3(512, 66), 256>>>();
    k_gemm_mma<<<dim3(4, 2, ZSPLIT), 256, SMEM_GEMM>>>();
    k_reduce<<<512, 256>>>((const float*)d_in[22]);
    k_enc2<<<dim3(8, 4), 256>>>((const float*)d_in[23], (const float*)d_in[24], (float*)d_out);
}

// round 10
// speedup vs baseline: 4.5850x; 1.0856x over previous
#include <cuda_runtime.h>
#include <cuda_fp16.h>
#include <math.h>
#include <stdint.h>

// Problem constants
#define BSZ   512
#define DD    64
#define DE    65
#define JK    4225      // 65*65
#define NOUT  256
#define KTOT  274625    // 65^3
#define KPAD  274688    // KTOT padded to multiple of 32
#define NCH_TOT 8584    // KPAD/32
#define ZSPLIT 36
#define CH_PER 239      // ceil(8584/36)

#define WSCALE   1024.0f
#define WSCALE_INV (1.0f/1024.0f)

// Scratch (static device arrays only)
__device__ float g_oe[3 * BSZ * DE];            // o1e/o2e/o3e with appended 1.0
__device__ float g_part[ZSPLIT * BSZ * NOUT];   // split-K partials [z][b][o]
__device__ float g_E[BSZ * 456];                // enc2 input
__device__ __align__(128) __half g_Wh[(size_t)NOUT * KPAD];  // W*1024 fp16
__device__ __align__(128) __half g_Bp[(size_t)BSZ * KPAD];   // B = o1*o2*o3 fp16

struct Ptrs { const float* p[25]; };

__device__ __forceinline__ uint32_t smem_u32(const void* p) {
    uint32_t a;
    asm("{ .reg .u64 t; cvta.to.shared.u64 t, %1; cvt.u32.u64 %0, t; }" : "=r"(a) : "l"(p));
    return a;
}
__device__ __forceinline__ void cp_async16(uint32_t dst, const void* src) {
    asm volatile("cp.async.cg.shared.global [%0], [%1], 16;" :: "r"(dst), "l"(src) : "memory");
}
__device__ __forceinline__ void mma_f16(float* d, const uint32_t* a, const uint32_t* b) {
    asm volatile("mma.sync.aligned.m16n8k16.row.col.f32.f16.f16.f32 "
        "{%0,%1,%2,%3}, {%4,%5,%6,%7}, {%8,%9}, {%0,%1,%2,%3};"
        : "+f"(d[0]), "+f"(d[1]), "+f"(d[2]), "+f"(d[3])
        : "r"(a[0]), "r"(a[1]), "r"(a[2]), "r"(a[3]), "r"(b[0]), "r"(b[1]));
}
__device__ __forceinline__ unsigned long long dup2(float x) {
    unsigned long long r;
    asm("mov.b64 %0, {%1, %1};" : "=l"(r) : "r"(__float_as_uint(x)));
    return r;
}
__device__ __forceinline__ void fma2(unsigned long long& acc, unsigned long long a, unsigned long long b) {
    asm("fma.rn.f32x2 %0, %1, %2, %0;" : "+l"(acc) : "l"(a), "l"(b));
}

// ---------------------------------------------------------------------------
// Kernel A: prep W -> single fp16 plane (scaled by 1024), padded/zeroed
// ---------------------------------------------------------------------------
__global__ __launch_bounds__(256) void k_prepW(const float* __restrict__ W) {
    int row = blockIdx.y;
    int k = (blockIdx.x * 256 + threadIdx.x) * 2;
    if (k >= KPAD) return;
    float w0 = (k     < KTOT) ? W[(size_t)row * KTOT + k]     * WSCALE : 0.f;
    float w1 = (k + 1 < KTOT) ? W[(size_t)row * KTOT + k + 1] * WSCALE : 0.f;
    *(__half2*)&g_Wh[(size_t)row * KPAD + k] =
        __halves2half2(__float2half_rn(w0), __float2half_rn(w1));
}

// ---------------------------------------------------------------------------
// Kernel 1: gated branches, SMEM-staged weights (coalesced zw slabs).
// ---------------------------------------------------------------------------
#define SMEM_BR ((3*16*64 + 2*64*65 + 64*65 + 16*64) * 4)   // 66304 B

__global__ __launch_bounds__(256) void k_branches(Ptrs P) {
    extern __shared__ float sm[];
    float* vs  = sm;               // [3][16][64]
    float* zsb = sm + 3072;        // [2][64][65]  slab [buf][j][o]
    float* ws  = zsb + 8320;       // [64][65]     staged hw / ow
    float* gsS = ws + 4160;        // [16][64]

    int b0 = blockIdx.x * 16;
    int br = blockIdx.y;
    int t = threadIdx.x;
    int o = t & 63, bg = t >> 6;

    const float* hw = P.p[3 + br * 6];
    const float* hb = P.p[4 + br * 6];
    const float* zw = P.p[5 + br * 6];
    const float* zb = P.p[6 + br * 6];
    const float* ow = P.p[7 + br * 6];
    const float* ob = P.p[8 + br * 6];
    int hv = br;
    int x1 = (br == 1) ? 1 : 0;

    #pragma unroll
    for (int q = 0; q < 4; q++) {
        int e = t + 256 * q;
        int bb = e >> 6, m = e & 63;
        vs[(0 * 16 + bb) * 64 + m] = P.p[0][(b0 + bb) * DD + m];
        vs[(1 * 16 + bb) * 64 + m] = P.p[1][(b0 + bb) * DD + m];
        vs[(2 * 16 + bb) * 64 + m] = P.p[2][(b0 + bb) * DD + m];
    }
    #pragma unroll
    for (int q = 0; q < 16; q++) {
        int e = t + 256 * q;
        int r = e >> 6, m = e & 63;
        ws[r * 65 + m] = hw[r * 64 + m];
    }
    #pragma unroll
    for (int q = 0; q < 16; q++) {
        int e = t + 256 * q;
        int oo = e >> 6, j = e & 63;
        zsb[j * 65 + oo] = zw[oo * 4096 + j];
    }
    __syncthreads();

    float hacc[4];
    #pragma unroll
    for (int q = 0; q < 4; q++) hacc[q] = hb[o];
    #pragma unroll 8
    for (int m = 0; m < DD; m++) {
        float w = ws[o * 65 + m];
        #pragma unroll
        for (int q = 0; q < 4; q++) hacc[q] += w * vs[(hv * 16 + bg * 4 + q) * 64 + m];
    }

    float zacc[4];
    #pragma unroll
    for (int q = 0; q < 4; q++) zacc[q] = zb[o];
    for (int i = 0; i < DD; i++) {
        float rt_[16];
        if (i + 1 < DD) {
            #pragma unroll
            for (int q = 0; q < 16; q++) {
                int e = t + 256 * q;
                int oo = e >> 6, j = e & 63;
                rt_[q] = zw[oo * 4096 + (i + 1) * 64 + j];
            }
        }
        const float* zc = zsb + (i & 1) * 4160;
        float s[4] = {0.f, 0.f, 0.f, 0.f};
        #pragma unroll 8
        for (int j = 0; j < DD; j++) {
            float zv = zc[j * 65 + o];
            #pragma unroll
            for (int q = 0; q < 4; q++) s[q] += zv * vs[(2 * 16 + bg * 4 + q) * 64 + j];
        }
        #pragma unroll
        for (int q = 0; q < 4; q++) zacc[q] += vs[(x1 * 16 + bg * 4 + q) * 64 + i] * s[q];
        if (i + 1 < DD) {
            float* zn = zsb + ((i + 1) & 1) * 4160;
            #pragma unroll
            for (int q = 0; q < 16; q++) {
                int e = t + 256 * q;
                int oo = e >> 6, j = e & 63;
                zn[j * 65 + oo] = rt_[q];
            }
        }
        __syncthreads();
    }

    #pragma unroll
    for (int q = 0; q < 16; q++) {
        int e = t + 256 * q;
        int r = e >> 6, m = e & 63;
        ws[r * 65 + m] = ow[r * 64 + m];
    }
    #pragma unroll
    for (int q = 0; q < 4; q++) {
        float h = fmaxf(hacc[q], 0.f);
        float sg = 1.f / (1.f + expf(-zacc[q]));
        gsS[(bg * 4 + q) * 64 + o] = h * sg;
    }
    __syncthreads();

    float oacc[4];
    #pragma unroll
    for (int q = 0; q < 4; q++) oacc[q] = ob[o];
    #pragma unroll 8
    for (int m = 0; m < DD; m++) {
        float w = ws[o * 65 + m];
        #pragma unroll
        for (int q = 0; q < 4; q++) oacc[q] += w * gsS[(bg * 4 + q) * 64 + m];
    }
    #pragma unroll
    for (int q = 0; q < 4; q++) {
        g_oe[((long long)br * BSZ + b0 + bg * 4 + q) * DE + o] = fmaxf(oacc[q], 0.f);
        if (o == 0) g_oe[((long long)br * BSZ + b0 + bg * 4 + q) * DE + DD] = 1.f;
    }
}

// ---------------------------------------------------------------------------
// Kernel 2: prep B plane fp16: Bp[b][i*4225+jk] = o1e[b,i]*o2e[b,j]*o3e[b,k]
// ---------------------------------------------------------------------------
__global__ __launch_bounds__(256) void k_prepB() {
    int b = blockIdx.x, i = blockIdx.y, t = threadIdx.x;
    if (i == 65) {
        if (t < KPAD - KTOT) g_Bp[(size_t)b * KPAD + KTOT + t] = __float2half_rn(0.f);
        return;
    }
    __shared__ float s2[DE], s3[DE];
    if (t < DE)           s2[t]      = g_oe[(1 * BSZ + b) * DE + t];
    else if (t < 2 * DE)  s3[t - DE] = g_oe[(2 * BSZ + b) * DE + (t - DE)];
    __syncthreads();
    float o1 = g_oe[(0 * BSZ + b) * DE + i];
    size_t base = (size_t)b * KPAD + (size_t)i * JK;
    bool aligned = ((i & 1) == 0);
    for (int e = t * 2; e < JK - 1; e += 512) {
        int j0 = e / DE, k0 = e - j0 * DE;
        float v0 = o1 * s2[j0] * s3[k0];
        int j1 = j0, k1 = k0 + 1;
        if (k1 == DE) { j1++; k1 = 0; }
        float v1 = o1 * s2[j1] * s3[k1];
        __half h0 = __float2half_rn(v0), h1 = __float2half_rn(v1);
        if (aligned) *(__half2*)&g_Bp[base + e] = __halves2half2(h0, h1);
        else { g_Bp[base + e] = h0; g_Bp[base + e + 1] = h1; }
    }
    if (t == 0)
        g_Bp[base + JK - 1] = __float2half_rn(o1 * s2[DE - 1] * s3[DE - 1]);
}

// ---------------------------------------------------------------------------
// Kernel 3: GEMM, mma.sync fp16, warp tile 64x64 (crossbar-relief).
// C[o 256, b 512] = sum_k Wh[o,k] * Bp[k,b]   (scaled by 1024)
// CTA tile 256(o) x 128(b), warp grid 4(m) x 2(n), chunk 32 k.
// Grid (4 btiles, 36 zsplits) = 144 CTAs. 4-stage cp.async pipeline.
// ---------------------------------------------------------------------------
#define SROW   80        // smem row stride (64B data + 16B pad)
#define A_ROWS 256
#define B_ROWS 128
#define BH_OFF (A_ROWS * SROW)            // 20480
#define STAGE  ((A_ROWS + B_ROWS) * SROW) // 30720
#define NST    4
#define SMEM_GEMM (NST * STAGE)           // 122880

__global__ __launch_bounds__(256, 1) void k_gemm_mma() {
    extern __shared__ char smem[];
    const uint32_t sb = smem_u32(smem);
    const int t = threadIdx.x, w = t >> 5, lane = t & 31;
    const int gid = lane >> 2, tig = lane & 3;
    const int warp_m = w >> 1, warp_n = w & 1;
    const int b0 = blockIdx.x * 128, z = blockIdx.y;
    const int c0 = z * CH_PER;
    const int nch = min(c0 + CH_PER, NCH_TOT) - c0;

    // cp.async descriptors: (256 A-rows + 128 B-rows) * 4 xfers = 1536 / 256 thr = 6
    const __half* srcb[6];
    uint32_t dsto[6];
    #pragma unroll
    for (int q = 0; q < 6; q++) {
        int e = t + 256 * q;
        if (e < 1024) {           // A plane: W rows (o = r)
            int r = e >> 2, qd = e & 3;
            srcb[q] = g_Wh + (size_t)r * KPAD + qd * 8;
            dsto[q] = (uint32_t)(r * SROW + qd * 16);
        } else {                  // B plane
            int e2 = e - 1024;
            int r = e2 >> 2, qd = e2 & 3;
            srcb[q] = g_Bp + (size_t)(b0 + r) * KPAD + qd * 8;
            dsto[q] = (uint32_t)(BH_OFF + r * SROW + qd * 16);
        }
    }

    float acc[4][8][4];
    #pragma unroll
    for (int mt = 0; mt < 4; mt++)
        #pragma unroll
        for (int nt = 0; nt < 8; nt++)
            #pragma unroll
            for (int q = 0; q < 4; q++) acc[mt][nt][q] = 0.f;

    // prologue
    #pragma unroll
    for (int p = 0; p < NST - 1; ++p) {
        if (p < nch) {
            int kb0 = (c0 + p) * 32;
            uint32_t stb = sb + (uint32_t)(p % NST) * STAGE;
            #pragma unroll
            for (int q = 0; q < 6; q++) cp_async16(stb + dsto[q], srcb[q] + kb0);
        }
        asm volatile("cp.async.commit_group;" ::: "memory");
    }

    for (int ci = 0; ci < nch; ++ci) {
        {
            int cf = ci + NST - 1;
            if (cf < nch) {
                int kb0 = (c0 + cf) * 32;
                uint32_t stb = sb + (uint32_t)(cf % NST) * STAGE;
                #pragma unroll
                for (int q = 0; q < 6; q++) cp_async16(stb + dsto[q], srcb[q] + kb0);
            }
            asm volatile("cp.async.commit_group;" ::: "memory");
        }
        asm volatile("cp.async.wait_group %0;" :: "n"(NST - 2) : "memory");
        __syncthreads();

        const char* sc = smem + (size_t)(ci % NST) * STAGE;
        #pragma unroll
        for (int kh = 0; kh < 2; ++kh) {
            uint32_t ah[4][4], bh[8][2];
            #pragma unroll
            for (int mt = 0; mt < 4; mt++) {
                uint32_t r0 = (uint32_t)(warp_m * 64 + mt * 16 + gid) * SROW + tig * 4 + kh * 32;
                ah[mt][0] = *(const uint32_t*)(sc + r0);
                ah[mt][1] = *(const uint32_t*)(sc + r0 + 8 * SROW);
                ah[mt][2] = *(const uint32_t*)(sc + r0 + 16);
                ah[mt][3] = *(const uint32_t*)(sc + r0 + 8 * SROW + 16);
            }
            #pragma unroll
            for (int nt = 0; nt < 8; nt++) {
                uint32_t r0 = (uint32_t)(BH_OFF + (warp_n * 64 + nt * 8 + gid) * SROW) + tig * 4 + kh * 32;
                bh[nt][0] = *(const uint32_t*)(sc + r0);
                bh[nt][1] = *(const uint32_t*)(sc + r0 + 16);
            }
            #pragma unroll
            for (int mt = 0; mt < 4; mt++)
                #pragma unroll
                for (int nt = 0; nt < 8; nt++)
                    mma_f16(acc[mt][nt], ah[mt], bh[nt]);
        }
        __syncthreads();
    }

    // epilogue: acc -> g_part[z][b][o]   (values carry the 1024x W scale)
    float* gp = g_part + (size_t)z * BSZ * NOUT;
    #pragma unroll
    for (int mt = 0; mt < 4; mt++) {
        int o = warp_m * 64 + mt * 16 + gid;
        #pragma unroll
        for (int nt = 0; nt < 8; nt++) {
            int b = b0 + warp_n * 64 + nt * 8 + tig * 2;
            gp[(size_t)b * NOUT + o]           = acc[mt][nt][0];
            gp[(size_t)(b + 1) * NOUT + o]     = acc[mt][nt][1];
            gp[(size_t)b * NOUT + o + 8]       = acc[mt][nt][2];
            gp[(size_t)(b + 1) * NOUT + o + 8] = acc[mt][nt][3];
        }
    }
}

// ---------------------------------------------------------------------------
// Kernel 4: reduce split-K partials (undo 1024x) + bias/relu + enc2 input
// ---------------------------------------------------------------------------
__global__ __launch_bounds__(256) void k_reduce(const float* __restrict__ e1b) {
    int b = blockIdx.x, t = threadIdx.x;
    float s = 0.f;
    #pragma unroll 6
    for (int zz = 0; zz < ZSPLIT; ++zz)
        s += g_part[((size_t)zz * BSZ + b) * NOUT + t];
    s = e1b[t] + s * WSCALE_INV;
    g_E[b * 456 + t] = fmaxf(s, 0.f);
    if (t < 195)
        g_E[b * 456 + 256 + t] = g_oe[((t / 65) * BSZ + b) * DE + (t % 65)];
    else if (t < 200)
        g_E[b * 456 + 451 + (t - 195)] = 0.f;
}

// ---------------------------------------------------------------------------
// Kernel 5: enc2 tiled GEMM: out[b,n] = relu(E[b,:451] . e2w[n,:451] + e2b[n])
// ---------------------------------------------------------------------------
__global__ __launch_bounds__(256) void k_enc2(const float* __restrict__ e2w,
                                              const float* __restrict__ e2b,
                                              float* __restrict__ out) {
    __shared__ __align__(16) float As[64][68];
    __shared__ __align__(16) float Bs[64][68];
    int b0 = blockIdx.x * 64, n0 = blockIdx.y * 64;
    int t = threadIdx.x;
    int m0 = (t >> 4) << 2, q0 = (t & 15) << 2;

    unsigned long long acc[4][2];
    #pragma unroll
    for (int a = 0; a < 4; a++)
        #pragma unroll
        for (int p = 0; p < 2; p++) acc[a][p] = 0ull;

    for (int kc = 0; kc < 512; kc += 64) {
        __syncthreads();
        for (int e = t; e < 64 * 64; e += 256) {
            int r = e >> 6, kk = e & 63;
            int k = kc + kk;
            As[kk][r] = (k < 451) ? e2w[(n0 + r) * 451 + k] : 0.f;
            Bs[kk][r] = (k < 451) ? g_E[(b0 + r) * 456 + k] : 0.f;
        }
        __syncthreads();
        #pragma unroll 16
        for (int kk = 0; kk < 64; ++kk) {
            float4 a4 = *(const float4*)&As[kk][m0];
            ulonglong2 bb = *(const ulonglong2*)&Bs[kk][q0];
            unsigned long long a0 = dup2(a4.x), a1 = dup2(a4.y),
                               a2 = dup2(a4.z), a3 = dup2(a4.w);
            fma2(acc[0][0], a0, bb.x); fma2(acc[0][1], a0, bb.y);
            fma2(acc[1][0], a1, bb.x); fma2(acc[1][1], a1, bb.y);
            fma2(acc[2][0], a2, bb.x); fma2(acc[2][1], a2, bb.y);
            fma2(acc[3][0], a3, bb.x); fma2(acc[3][1], a3, bb.y);
        }
    }

    #pragma unroll
    for (int mi = 0; mi < 4; ++mi) {
        int n = n0 + m0 + mi;
        float bias = e2b[n];
        #pragma unroll
        for (int p = 0; p < 2; ++p) {
            unsigned long long v = acc[mi][p];
            float lo = __uint_as_float((unsigned)v);
            float hi = __uint_as_float((unsigned)(v >> 32));
            out[(b0 + q0 + 2 * p)     * NOUT + n] = fmaxf(lo + bias, 0.f);
            out[(b0 + q0 + 2 * p + 1) * NOUT + n] = fmaxf(hi + bias, 0.f);
        }
    }
}

// ---------------------------------------------------------------------------
extern "C" void kernel_launch(void* const* d_in, const int* in_sizes, int n_in,
                              void* d_out, int out_size) {
    Ptrs P;
    for (int i = 0; i < 25; i++) P.p[i] = (const float*)d_in[i];

    cudaFuncSetAttribute(k_gemm_mma, cudaFuncAttributeMaxDynamicSharedMemorySize, SMEM_GEMM);
    cudaFuncSetAttribute(k_branches, cudaFuncAttributeMaxDynamicSharedMemorySize, SMEM_BR);

    k_prepW<<<dim3((KPAD / 2 + 255) / 256, 256), 256>>>((const float*)d_in[21]);
    k_branches<<<dim3(32, 3), 256, SMEM_BR>>>(P);
    k_prepB<<<dim3(512, 66), 256>>>();
    k_gemm_mma<<<dim3(4, ZSPLIT), 256, SMEM_GEMM>>>();
    k_reduce<<<512, 256>>>((const float*)d_in[22]);
    k_enc2<<<dim3(8, 4), 256>>>((const float*)d_in[23], (const float*)d_in[24], (float*)d_out);
}

// round 11
// speedup vs baseline: 4.8315x; 1.0538x over previous
#include <cuda_runtime.h>
#include <cuda_fp16.h>
#include <math.h>
#include <stdint.h>

// Problem constants
#define BSZ   512
#define DD    64
#define DE    65
#define JK    4225      // 65*65
#define NOUT  256
#define KTOT  274625    // 65^3
#define KPAD  274688    // KTOT padded to multiple of 32
#define NCH_TOT 8584    // KPAD/32
#define ZSPLIT 37
#define CH_PER 232      // 37*232 = 8584 exact

#define WSCALE   1024.0f
#define WSCALE_INV (1.0f/1024.0f)

// Scratch (static device arrays only)
__device__ float g_oe[3 * BSZ * DE];            // o1e/o2e/o3e with appended 1.0
__device__ float g_part[ZSPLIT * BSZ * NOUT];   // split-K partials [z][b][o]
__device__ float g_E[BSZ * 456];                // enc2 input
__device__ __align__(128) __half g_Wh[(size_t)NOUT * KPAD];  // W*1024 fp16
__device__ __align__(128) __half g_Bp[(size_t)BSZ * KPAD];   // B = o1*o2*o3 fp16

struct Ptrs { const float* p[25]; };

__device__ __forceinline__ uint32_t smem_u32(const void* p) {
    uint32_t a;
    asm("{ .reg .u64 t; cvta.to.shared.u64 t, %1; cvt.u32.u64 %0, t; }" : "=r"(a) : "l"(p));
    return a;
}
__device__ __forceinline__ void cp_async16(uint32_t dst, const void* src) {
    asm volatile("cp.async.cg.shared.global [%0], [%1], 16;" :: "r"(dst), "l"(src) : "memory");
}
__device__ __forceinline__ void ldsm_x4(uint32_t* r, uint32_t addr) {
    asm volatile("ldmatrix.sync.aligned.m8n8.x4.shared.b16 {%0,%1,%2,%3}, [%4];"
        : "=r"(r[0]), "=r"(r[1]), "=r"(r[2]), "=r"(r[3]) : "r"(addr));
}
__device__ __forceinline__ void mma_f16(float* d, const uint32_t* a, const uint32_t* b) {
    asm volatile("mma.sync.aligned.m16n8k16.row.col.f32.f16.f16.f32 "
        "{%0,%1,%2,%3}, {%4,%5,%6,%7}, {%8,%9}, {%0,%1,%2,%3};"
        : "+f"(d[0]), "+f"(d[1]), "+f"(d[2]), "+f"(d[3])
        : "r"(a[0]), "r"(a[1]), "r"(a[2]), "r"(a[3]), "r"(b[0]), "r"(b[1]));
}
__device__ __forceinline__ unsigned long long dup2(float x) {
    unsigned long long r;
    asm("mov.b64 %0, {%1, %1};" : "=l"(r) : "r"(__float_as_uint(x)));
    return r;
}
__device__ __forceinline__ void fma2(unsigned long long& acc, unsigned long long a, unsigned long long b) {
    asm("fma.rn.f32x2 %0, %1, %2, %0;" : "+l"(acc) : "l"(a), "l"(b));
}

// ---------------------------------------------------------------------------
// Kernel A: prep W -> single fp16 plane (scaled by 1024), padded/zeroed
// ---------------------------------------------------------------------------
__global__ __launch_bounds__(256) void k_prepW(const float* __restrict__ W) {
    int row = blockIdx.y;
    int k = (blockIdx.x * 256 + threadIdx.x) * 2;
    if (k >= KPAD) return;
    float w0 = (k     < KTOT) ? W[(size_t)row * KTOT + k]     * WSCALE : 0.f;
    float w1 = (k + 1 < KTOT) ? W[(size_t)row * KTOT + k + 1] * WSCALE : 0.f;
    *(__half2*)&g_Wh[(size_t)row * KPAD + k] =
        __halves2half2(__float2half_rn(w0), __float2half_rn(w1));
}

// ---------------------------------------------------------------------------
// Kernel 1: gated branches, SMEM-staged weights (coalesced zw slabs).
// ---------------------------------------------------------------------------
#define SMEM_BR ((3*16*64 + 2*64*65 + 64*65 + 16*64) * 4)   // 66304 B

__global__ __launch_bounds__(256) void k_branches(Ptrs P) {
    extern __shared__ float sm[];
    float* vs  = sm;               // [3][16][64]
    float* zsb = sm + 3072;        // [2][64][65]  slab [buf][j][o]
    float* ws  = zsb + 8320;       // [64][65]     staged hw / ow
    float* gsS = ws + 4160;        // [16][64]

    int b0 = blockIdx.x * 16;
    int br = blockIdx.y;
    int t = threadIdx.x;
    int o = t & 63, bg = t >> 6;

    const float* hw = P.p[3 + br * 6];
    const float* hb = P.p[4 + br * 6];
    const float* zw = P.p[5 + br * 6];
    const float* zb = P.p[6 + br * 6];
    const float* ow = P.p[7 + br * 6];
    const float* ob = P.p[8 + br * 6];
    int hv = br;
    int x1 = (br == 1) ? 1 : 0;

    #pragma unroll
    for (int q = 0; q < 4; q++) {
        int e = t + 256 * q;
        int bb = e >> 6, m = e & 63;
        vs[(0 * 16 + bb) * 64 + m] = P.p[0][(b0 + bb) * DD + m];
        vs[(1 * 16 + bb) * 64 + m] = P.p[1][(b0 + bb) * DD + m];
        vs[(2 * 16 + bb) * 64 + m] = P.p[2][(b0 + bb) * DD + m];
    }
    #pragma unroll
    for (int q = 0; q < 16; q++) {
        int e = t + 256 * q;
        int r = e >> 6, m = e & 63;
        ws[r * 65 + m] = hw[r * 64 + m];
    }
    #pragma unroll
    for (int q = 0; q < 16; q++) {
        int e = t + 256 * q;
        int oo = e >> 6, j = e & 63;
        zsb[j * 65 + oo] = zw[oo * 4096 + j];
    }
    __syncthreads();

    float hacc[4];
    #pragma unroll
    for (int q = 0; q < 4; q++) hacc[q] = hb[o];
    #pragma unroll 8
    for (int m = 0; m < DD; m++) {
        float w = ws[o * 65 + m];
        #pragma unroll
        for (int q = 0; q < 4; q++) hacc[q] += w * vs[(hv * 16 + bg * 4 + q) * 64 + m];
    }

    float zacc[4];
    #pragma unroll
    for (int q = 0; q < 4; q++) zacc[q] = zb[o];
    for (int i = 0; i < DD; i++) {
        float rt_[16];
        if (i + 1 < DD) {
            #pragma unroll
            for (int q = 0; q < 16; q++) {
                int e = t + 256 * q;
                int oo = e >> 6, j = e & 63;
                rt_[q] = zw[oo * 4096 + (i + 1) * 64 + j];
            }
        }
        const float* zc = zsb + (i & 1) * 4160;
        float s[4] = {0.f, 0.f, 0.f, 0.f};
        #pragma unroll 8
        for (int j = 0; j < DD; j++) {
            float zv = zc[j * 65 + o];
            #pragma unroll
            for (int q = 0; q < 4; q++) s[q] += zv * vs[(2 * 16 + bg * 4 + q) * 64 + j];
        }
        #pragma unroll
        for (int q = 0; q < 4; q++) zacc[q] += vs[(x1 * 16 + bg * 4 + q) * 64 + i] * s[q];
        if (i + 1 < DD) {
            float* zn = zsb + ((i + 1) & 1) * 4160;
            #pragma unroll
            for (int q = 0; q < 16; q++) {
                int e = t + 256 * q;
                int oo = e >> 6, j = e & 63;
                zn[j * 65 + oo] = rt_[q];
            }
        }
        __syncthreads();
    }

    #pragma unroll
    for (int q = 0; q < 16; q++) {
        int e = t + 256 * q;
        int r = e >> 6, m = e & 63;
        ws[r * 65 + m] = ow[r * 64 + m];
    }
    #pragma unroll
    for (int q = 0; q < 4; q++) {
        float h = fmaxf(hacc[q], 0.f);
        float sg = 1.f / (1.f + expf(-zacc[q]));
        gsS[(bg * 4 + q) * 64 + o] = h * sg;
    }
    __syncthreads();

    float oacc[4];
    #pragma unroll
    for (int q = 0; q < 4; q++) oacc[q] = ob[o];
    #pragma unroll 8
    for (int m = 0; m < DD; m++) {
        float w = ws[o * 65 + m];
        #pragma unroll
        for (int q = 0; q < 4; q++) oacc[q] += w * gsS[(bg * 4 + q) * 64 + m];
    }
    #pragma unroll
    for (int q = 0; q < 4; q++) {
        g_oe[((long long)br * BSZ + b0 + bg * 4 + q) * DE + o] = fmaxf(oacc[q], 0.f);
        if (o == 0) g_oe[((long long)br * BSZ + b0 + bg * 4 + q) * DE + DD] = 1.f;
    }
}

// ---------------------------------------------------------------------------
// Kernel 2: prep B plane fp16: Bp[b][i*4225+jk] = o1e[b,i]*o2e[b,j]*o3e[b,k]
// ---------------------------------------------------------------------------
__global__ __launch_bounds__(256) void k_prepB() {
    int b = blockIdx.x, i = blockIdx.y, t = threadIdx.x;
    if (i == 65) {
        if (t < KPAD - KTOT) g_Bp[(size_t)b * KPAD + KTOT + t] = __float2half_rn(0.f);
        return;
    }
    __shared__ float s2[DE], s3[DE];
    if (t < DE)           s2[t]      = g_oe[(1 * BSZ + b) * DE + t];
    else if (t < 2 * DE)  s3[t - DE] = g_oe[(2 * BSZ + b) * DE + (t - DE)];
    __syncthreads();
    float o1 = g_oe[(0 * BSZ + b) * DE + i];
    size_t base = (size_t)b * KPAD + (size_t)i * JK;
    bool aligned = ((i & 1) == 0);
    for (int e = t * 2; e < JK - 1; e += 512) {
        int j0 = e / DE, k0 = e - j0 * DE;
        float v0 = o1 * s2[j0] * s3[k0];
        int j1 = j0, k1 = k0 + 1;
        if (k1 == DE) { j1++; k1 = 0; }
        float v1 = o1 * s2[j1] * s3[k1];
        __half h0 = __float2half_rn(v0), h1 = __float2half_rn(v1);
        if (aligned) *(__half2*)&g_Bp[base + e] = __halves2half2(h0, h1);
        else { g_Bp[base + e] = h0; g_Bp[base + e + 1] = h1; }
    }
    if (t == 0)
        g_Bp[base + JK - 1] = __float2half_rn(o1 * s2[DE - 1] * s3[DE - 1]);
}

// ---------------------------------------------------------------------------
// Kernel 3: GEMM, mma.sync fp16, 512 threads, 4x4 warp grid (64x32 tiles),
// ldmatrix.x4 fragment loads. CTA tile 256(o) x 128(b), chunk 32 k.
// Grid (4 btiles, 37 zsplits) = 148 CTAs = one full wave.
// ---------------------------------------------------------------------------
#define SROW   80        // smem row stride (64B data + 16B pad)
#define A_ROWS 256
#define B_ROWS 128
#define BH_OFF (A_ROWS * SROW)            // 20480
#define STAGE  ((A_ROWS + B_ROWS) * SROW) // 30720
#define NST    4
#define SMEM_GEMM (NST * STAGE)           // 122880

__global__ __launch_bounds__(512, 1) void k_gemm_mma() {
    extern __shared__ char smem[];
    const uint32_t sb = smem_u32(smem);
    const int t = threadIdx.x, w = t >> 5, lane = t & 31;
    const int gid = lane >> 2, tig = lane & 3;
    const int warp_m = w >> 2, warp_n = w & 3;
    const int b0 = blockIdx.x * 128, z = blockIdx.y;
    const int c0 = z * CH_PER;
    const int nch = CH_PER;  // 37*232 = 8584 exact

    // cp.async descriptors: 1536 16B-xfers / 512 thr = 3
    const __half* srcb[3];
    uint32_t dsto[3];
    #pragma unroll
    for (int q = 0; q < 3; q++) {
        int e = t + 512 * q;
        if (e < 1024) {           // A plane: W rows
            int r = e >> 2, qd = e & 3;
            srcb[q] = g_Wh + (size_t)r * KPAD + qd * 8;
            dsto[q] = (uint32_t)(r * SROW + qd * 16);
        } else {                  // B plane
            int e2 = e - 1024;
            int r = e2 >> 2, qd = e2 & 3;
            srcb[q] = g_Bp + (size_t)(b0 + r) * KPAD + qd * 8;
            dsto[q] = (uint32_t)(BH_OFF + r * SROW + qd * 16);
        }
    }

    // ldmatrix lane-offsets (within a stage)
    // A m16k16 tile (mt): lanes 0-15 rows, lanes16-31 same rows +16B (k8-15)
    uint32_t a_off[4];
    #pragma unroll
    for (int mt = 0; mt < 4; mt++)
        a_off[mt] = (uint32_t)((warp_m * 64 + mt * 16 + (lane & 15)) * SROW + (lane >> 4) * 16);
    // B n16k16 (np covers nt pair): lanes0-7 n0-7 k0-7, 8-15 n0-7 k8-15,
    //                               16-23 n8-15 k0-7, 24-31 n8-15 k8-15
    uint32_t b_off[2];
    #pragma unroll
    for (int np = 0; np < 2; np++)
        b_off[np] = (uint32_t)(BH_OFF +
            (warp_n * 32 + np * 16 + ((lane >> 4) * 8 + (lane & 7))) * SROW +
            ((lane >> 3) & 1) * 16);

    float acc[4][4][4];
    #pragma unroll
    for (int mt = 0; mt < 4; mt++)
        #pragma unroll
        for (int nt = 0; nt < 4; nt++)
            #pragma unroll
            for (int q = 0; q < 4; q++) acc[mt][nt][q] = 0.f;

    // prologue
    #pragma unroll
    for (int p = 0; p < NST - 1; ++p) {
        int kb0 = (c0 + p) * 32;
        uint32_t stb = sb + (uint32_t)(p % NST) * STAGE;
        #pragma unroll
        for (int q = 0; q < 3; q++) cp_async16(stb + dsto[q], srcb[q] + kb0);
        asm volatile("cp.async.commit_group;" ::: "memory");
    }

    for (int ci = 0; ci < nch; ++ci) {
        {
            int cf = ci + NST - 1;
            if (cf < nch) {
                int kb0 = (c0 + cf) * 32;
                uint32_t stb = sb + (uint32_t)(cf % NST) * STAGE;
                #pragma unroll
                for (int q = 0; q < 3; q++) cp_async16(stb + dsto[q], srcb[q] + kb0);
            }
            asm volatile("cp.async.commit_group;" ::: "memory");
        }
        asm volatile("cp.async.wait_group %0;" :: "n"(NST - 2) : "memory");
        __syncthreads();

        const uint32_t st = sb + (uint32_t)(ci % NST) * STAGE;
        #pragma unroll
        for (int kh = 0; kh < 2; ++kh) {
            uint32_t bh[4][2];
            #pragma unroll
            for (int np = 0; np < 2; np++) {
                uint32_t r4[4];
                ldsm_x4(r4, st + b_off[np] + kh * 32);
                bh[np * 2][0]     = r4[0];
                bh[np * 2][1]     = r4[1];
                bh[np * 2 + 1][0] = r4[2];
                bh[np * 2 + 1][1] = r4[3];
            }
            #pragma unroll
            for (int mt = 0; mt < 4; mt++) {
                uint32_t a4[4];
                ldsm_x4(a4, st + a_off[mt] + kh * 32);
                #pragma unroll
                for (int nt = 0; nt < 4; nt++)
                    mma_f16(acc[mt][nt], a4, bh[nt]);
            }
        }
        __syncthreads();
    }

    // epilogue: acc -> g_part[z][b][o]   (values carry the 1024x W scale)
    float* gp = g_part + (size_t)z * BSZ * NOUT;
    #pragma unroll
    for (int mt = 0; mt < 4; mt++) {
        int o = warp_m * 64 + mt * 16 + gid;
        #pragma unroll
        for (int nt = 0; nt < 4; nt++) {
            int b = b0 + warp_n * 32 + nt * 8 + tig * 2;
            gp[(size_t)b * NOUT + o]           = acc[mt][nt][0];
            gp[(size_t)(b + 1) * NOUT + o]     = acc[mt][nt][1];
            gp[(size_t)b * NOUT + o + 8]       = acc[mt][nt][2];
            gp[(size_t)(b + 1) * NOUT + o + 8] = acc[mt][nt][3];
        }
    }
}

// ---------------------------------------------------------------------------
// Kernel 4: reduce split-K partials (undo 1024x) + bias/relu + enc2 input
// ---------------------------------------------------------------------------
__global__ __launch_bounds__(256) void k_reduce(const float* __restrict__ e1b) {
    int b = blockIdx.x, t = threadIdx.x;
    float s = 0.f;
    #pragma unroll 1
    for (int zz = 0; zz < ZSPLIT; ++zz)
        s += g_part[((size_t)zz * BSZ + b) * NOUT + t];
    s = e1b[t] + s * WSCALE_INV;
    g_E[b * 456 + t] = fmaxf(s, 0.f);
    if (t < 195)
        g_E[b * 456 + 256 + t] = g_oe[((t / 65) * BSZ + b) * DE + (t % 65)];
    else if (t < 200)
        g_E[b * 456 + 451 + (t - 195)] = 0.f;
}

// ---------------------------------------------------------------------------
// Kernel 5: enc2 tiled GEMM: out[b,n] = relu(E[b,:451] . e2w[n,:451] + e2b[n])
// ---------------------------------------------------------------------------
__global__ __launch_bounds__(256) void k_enc2(const float* __restrict__ e2w,
                                              const float* __restrict__ e2b,
                                              float* __restrict__ out) {
    __shared__ __align__(16) float As[64][68];
    __shared__ __align__(16) float Bs[64][68];
    int b0 = blockIdx.x * 64, n0 = blockIdx.y * 64;
    int t = threadIdx.x;
    int m0 = (t >> 4) << 2, q0 = (t & 15) << 2;

    unsigned long long acc[4][2];
    #pragma unroll
    for (int a = 0; a < 4; a++)
        #pragma unroll
        for (int p = 0; p < 2; p++) acc[a][p] = 0ull;

    for (int kc = 0; kc < 512; kc += 64) {
        __syncthreads();
        for (int e = t; e < 64 * 64; e += 256) {
            int r = e >> 6, kk = e & 63;
            int k = kc + kk;
            As[kk][r] = (k < 451) ? e2w[(n0 + r) * 451 + k] : 0.f;
            Bs[kk][r] = (k < 451) ? g_E[(b0 + r) * 456 + k] : 0.f;
        }
        __syncthreads();
        #pragma unroll 16
        for (int kk = 0; kk < 64; ++kk) {
            float4 a4 = *(const float4*)&As[kk][m0];
            ulonglong2 bb = *(const ulonglong2*)&Bs[kk][q0];
            unsigned long long a0 = dup2(a4.x), a1 = dup2(a4.y),
                               a2 = dup2(a4.z), a3 = dup2(a4.w);
            fma2(acc[0][0], a0, bb.x); fma2(acc[0][1], a0, bb.y);
            fma2(acc[1][0], a1, bb.x); fma2(acc[1][1], a1, bb.y);
            fma2(acc[2][0], a2, bb.x); fma2(acc[2][1], a2, bb.y);
            fma2(acc[3][0], a3, bb.x); fma2(acc[3][1], a3, bb.y);
        }
    }

    #pragma unroll
    for (int mi = 0; mi < 4; ++mi) {
        int n = n0 + m0 + mi;
        float bias = e2b[n];
        #pragma unroll
        for (int p = 0; p < 2; ++p) {
            unsigned long long v = acc[mi][p];
            float lo = __uint_as_float((unsigned)v);
            float hi = __uint_as_float((unsigned)(v >> 32));
            out[(b0 + q0 + 2 * p)     * NOUT + n] = fmaxf(lo + bias, 0.f);
            out[(b0 + q0 + 2 * p + 1) * NOUT + n] = fmaxf(hi + bias, 0.f);
        }
    }
}

// ---------------------------------------------------------------------------
extern "C" void kernel_launch(void* const* d_in, const int* in_sizes, int n_in,
                              void* d_out, int out_size) {
    Ptrs P;
    for (int i = 0; i < 25; i++) P.p[i] = (const float*)d_in[i];

    cudaFuncSetAttribute(k_gemm_mma, cudaFuncAttributeMaxDynamicSharedMemorySize, SMEM_GEMM);
    cudaFuncSetAttribute(k_branches, cudaFuncAttributeMaxDynamicSharedMemorySize, SMEM_BR);

    k_prepW<<<dim3((KPAD / 2 + 255) / 256, 256), 256>>>((const float*)d_in[21]);
    k_branches<<<dim3(32, 3), 256, SMEM_BR>>>(P);
    k_prepB<<<dim3(512, 66), 256>>>();
    k_gemm_mma<<<dim3(4, ZSPLIT), 512, SMEM_GEMM>>>();
    k_reduce<<<512, 256>>>((const float*)d_in[22]);
    k_enc2<<<dim3(8, 4), 256>>>((const float*)d_in[23], (const float*)d_in[24], (float*)d_out);
}